// round 3
// baseline (speedup 1.0000x reference)
#include <cuda_runtime.h>
#include <cstdint>

// Problem constants
#define B_  8
#define N_  1024
#define C_  256
#define H_  8
#define HD_ 64
#define BH_ (B_ * H_)            // 64
#define HEAD_ELEMS_ 524288       // B*N*HD per head
#define SCALE_ 0.0625f           // 1/sqrt(256)
#define SROW 1025                // padded smem row stride for scores slab

// Scratch (device globals: allocation-free rule)
__device__ float g_q[BH_ * N_ * HD_];        // [b,h,n,d] normalized Q, 16 MB
__device__ float g_k[BH_ * N_ * HD_];        // 16 MB
__device__ float g_part[1024 * 2];           // per-block partial (sum, sumsq)
__device__ float g_stats[16 * 2];            // [t*8+h]: mean, rstd

// ---------------------------------------------------------------------------
// Kernel 1: q = x @ qw^T, k = x @ kw^T   (M=8192, Ncols=512, K=256) — fp32 FFMA
// ---------------------------------------------------------------------------
__global__ void __launch_bounds__(256) gemm_qk_kernel(const float* __restrict__ x,
                                                      const float* __restrict__ qw,
                                                      const float* __restrict__ kw) {
    __shared__ float As[16][132];
    __shared__ float Bs[16][132];
    const int tid = threadIdx.x;
    const float* wptr = blockIdx.z ? kw : qw;
    float* outp = blockIdx.z ? g_k : g_q;
    const int m0 = blockIdx.y * 128;
    const int n0 = blockIdx.x * 128;
    const int tx = tid & 15, ty = tid >> 4;

    float acc[8][8];
#pragma unroll
    for (int i = 0; i < 8; i++)
#pragma unroll
        for (int j = 0; j < 8; j++) acc[i][j] = 0.f;

    for (int kt = 0; kt < C_; kt += 16) {
#pragma unroll
        for (int i = 0; i < 2; i++) {
            int idx = tid + i * 256;
            int r = idx >> 2;
            int kq = idx & 3;
            float4 va = *(const float4*)(x + (size_t)(m0 + r) * C_ + kt + kq * 4);
            As[kq * 4 + 0][r] = va.x; As[kq * 4 + 1][r] = va.y;
            As[kq * 4 + 2][r] = va.z; As[kq * 4 + 3][r] = va.w;
            float4 vb = *(const float4*)(wptr + (size_t)(n0 + r) * C_ + kt + kq * 4);
            Bs[kq * 4 + 0][r] = vb.x; Bs[kq * 4 + 1][r] = vb.y;
            Bs[kq * 4 + 2][r] = vb.z; Bs[kq * 4 + 3][r] = vb.w;
        }
        __syncthreads();
#pragma unroll
        for (int kk = 0; kk < 16; kk++) {
            float a[8], bv[8];
            *(float4*)(a)     = *(const float4*)&As[kk][ty * 8];
            *(float4*)(a + 4) = *(const float4*)&As[kk][ty * 8 + 4];
            *(float4*)(bv)     = *(const float4*)&Bs[kk][tx * 8];
            *(float4*)(bv + 4) = *(const float4*)&Bs[kk][tx * 8 + 4];
#pragma unroll
            for (int i = 0; i < 8; i++)
#pragma unroll
                for (int j = 0; j < 8; j++) acc[i][j] = fmaf(a[i], bv[j], acc[i][j]);
        }
        __syncthreads();
    }
    const int col0 = n0 + tx * 8;
    const int h = col0 >> 6;
    const int d0 = col0 & 63;
#pragma unroll
    for (int i = 0; i < 8; i++) {
        int row = m0 + ty * 8 + i;
        int bb = row >> 10, nn = row & 1023;
        float* dst = outp + ((size_t)(bb * H_ + h) << 16) + nn * 64 + d0;
        *(float4*)dst       = make_float4(acc[i][0], acc[i][1], acc[i][2], acc[i][3]);
        *(float4*)(dst + 4) = make_float4(acc[i][4], acc[i][5], acc[i][6], acc[i][7]);
    }
}

// ---------------------------------------------------------------------------
// Kernel 2: per-(tensor,head) partial sums for BN stats. 1024 blocks.
// ---------------------------------------------------------------------------
__global__ void __launch_bounds__(256) bn_partial_kernel() {
    int bid = blockIdx.x;
    int t = bid >> 9;
    int rest = bid & 511;
    int h = rest >> 6;
    int s = rest & 63;
    int b = s >> 3, chunk = s & 7;
    const float* p = (t ? g_k : g_q) + (size_t)(b * H_ + h) * 65536 + chunk * 8192;
    const float4* p4 = (const float4*)p;
    int tid = threadIdx.x;
    float s1 = 0.f, s2 = 0.f;
#pragma unroll
    for (int j = 0; j < 8; j++) {
        float4 v = p4[tid + j * 256];
        s1 += v.x + v.y + v.z + v.w;
        s2 += v.x * v.x + v.y * v.y + v.z * v.z + v.w * v.w;
    }
#pragma unroll
    for (int o = 16; o; o >>= 1) {
        s1 += __shfl_xor_sync(0xffffffffu, s1, o);
        s2 += __shfl_xor_sync(0xffffffffu, s2, o);
    }
    __shared__ float red[16];
    if ((tid & 31) == 0) { red[(tid >> 5) * 2] = s1; red[(tid >> 5) * 2 + 1] = s2; }
    __syncthreads();
    if (tid == 0) {
        float a = 0.f, c = 0.f;
        for (int wq = 0; wq < 8; wq++) { a += red[wq * 2]; c += red[wq * 2 + 1]; }
        g_part[bid * 2] = a;
        g_part[bid * 2 + 1] = c;
    }
}

__global__ void bn_finalize_kernel() {
    int tid = threadIdx.x;
    if (tid < 16) {
        int t = tid >> 3, h = tid & 7;
        int base = t * 512 + h * 64;
        float s1 = 0.f, s2 = 0.f;
        for (int s = 0; s < 64; s++) {
            s1 += g_part[(base + s) * 2];
            s2 += g_part[(base + s) * 2 + 1];
        }
        float mean = s1 * (1.f / (float)HEAD_ELEMS_);
        float var = s2 * (1.f / (float)HEAD_ELEMS_) - mean * mean;
        g_stats[tid * 2] = mean;
        g_stats[tid * 2 + 1] = rsqrtf(var + 1e-5f);
    }
}

// ---------------------------------------------------------------------------
// Kernel 3: apply BN (affine) + L2 normalize each 64-row, in place.
// ---------------------------------------------------------------------------
__global__ void __launch_bounds__(256) normalize_kernel(const float* __restrict__ bnw,
                                                        const float* __restrict__ bnb) {
    int gw = (blockIdx.x * blockDim.x + threadIdx.x) >> 5;
    int lane = threadIdx.x & 31;
    int t = gw >> 16;
    int rem = gw & 65535;
    int h = (rem >> 10) & 7;
    float* p = (t ? g_k : g_q) + (size_t)rem * 64;
    float mean = g_stats[(t * 8 + h) * 2];
    float rstd = g_stats[(t * 8 + h) * 2 + 1];
    float w = bnw[h], bia = bnb[h];
    float2 v = *(float2*)(p + lane * 2);
    float x0 = (v.x - mean) * rstd * w + bia;
    float x1 = (v.y - mean) * rstd * w + bia;
    float ss = x0 * x0 + x1 * x1;
#pragma unroll
    for (int o = 16; o; o >>= 1) ss += __shfl_xor_sync(0xffffffffu, ss, o);
    float nrm = sqrtf(ss);
    float inv = 1.f / fmaxf(nrm, 1e-12f);
    v.x = x0 * inv; v.y = x1 * inv;
    *(float2*)(p + lane * 2) = v;
}

// ---------------------------------------------------------------------------
// Kernel 4 (fused): per (b,h, 32-row m-tile): scores slab [32 x 1024] via
// 3xTF32 mma.sync (fp32-accurate), sparsemax (Michelot) in smem, transposed
// coalesced write to out[b, n, h*1024+m]. No scores tensor in DRAM.
// ---------------------------------------------------------------------------
__device__ __forceinline__ unsigned f2tf32(float a) {
    unsigned r; asm("cvt.rna.tf32.f32 %0, %1;" : "=r"(r) : "f"(a)); return r;
}
__device__ __forceinline__ void mma8(float* c, const unsigned* a, unsigned b0, unsigned b1) {
    asm volatile("mma.sync.aligned.m16n8k8.row.col.f32.tf32.tf32.f32 "
                 "{%0,%1,%2,%3},{%4,%5,%6,%7},{%8,%9},{%0,%1,%2,%3};"
                 : "+f"(c[0]), "+f"(c[1]), "+f"(c[2]), "+f"(c[3])
                 : "r"(a[0]), "r"(a[1]), "r"(a[2]), "r"(a[3]), "r"(b0), "r"(b1));
}

// smem: S_s[32][1025] | Q_s[2][1024][8] | K_s[32][66] | tau[32]
#define FUSED_SMEM_FLOATS (32 * SROW + 2 * 8192 + 32 * 66 + 32)
#define FUSED_SMEM_BYTES  (FUSED_SMEM_FLOATS * 4)

__global__ void __launch_bounds__(512) fused_scores_sparsemax(float* __restrict__ out) {
    extern __shared__ float sm[];
    float* S_s  = sm;
    float* Q_s  = sm + 32 * SROW;
    float* K_s  = Q_s + 2 * 8192;
    float* tau_s = K_s + 32 * 66;

    const int tid = threadIdx.x;
    const int w = tid >> 5, lane = tid & 31;
    const int gid = lane >> 2, tg = lane & 3;
    const int bh = blockIdx.y;
    const int m0 = blockIdx.x * 32;
    const float* Qh = g_q + (size_t)bh * 65536;
    const float* Kh = g_k + (size_t)bh * 65536;

    // Stage K tile [32][64] once (stride-66 pad)
    {
        int mrow = tid >> 4;           // 0..31
        int q4 = tid & 15;             // float4 index 0..15
        float4 v = *(const float4*)(Kh + (size_t)(m0 + mrow) * 64 + q4 * 4);
        float* d = K_s + mrow * 66 + q4 * 4;
        d[0] = v.x; d[1] = v.y; d[2] = v.z; d[3] = v.w;
    }

    float c[2][8][4];
#pragma unroll
    for (int mt = 0; mt < 2; mt++)
#pragma unroll
        for (int nt = 0; nt < 8; nt++)
#pragma unroll
            for (int j = 0; j < 4; j++) c[mt][nt][j] = 0.f;

    // Stage Q k-slice 0 into buffer 0
#pragma unroll
    for (int i = 0; i < 2; i++) {
        int slot = tid + i * 512;                          // row n
        const float4* src = (const float4*)(Qh + (size_t)slot * 64);
        float* d = Q_s + slot * 8;
        *(float4*)d = src[0]; *(float4*)(d + 4) = src[1];
    }
    __syncthreads();

    int buf = 0;
    for (int kt = 0; kt < 8; kt++) {
        // Prefetch next Q k-slice into the other buffer (overlaps with MMA)
        if (kt < 7) {
            float* dst = Q_s + (buf ^ 1) * 8192;
#pragma unroll
            for (int i = 0; i < 2; i++) {
                int slot = tid + i * 512;
                const float4* src = (const float4*)(Qh + (size_t)slot * 64 + (kt + 1) * 8);
                float* d = dst + slot * 8;
                *(float4*)d = src[0]; *(float4*)(d + 4) = src[1];
            }
        }

        // A fragments (K tile), hi/lo tf32 split
        unsigned ahi[2][4], alo[2][4];
#pragma unroll
        for (int mt = 0; mt < 2; mt++) {
            const float* kp = K_s + (mt * 16 + gid) * 66 + kt * 8 + tg;
            float av[4];
            av[0] = kp[0]; av[1] = kp[8 * 66]; av[2] = kp[4]; av[3] = kp[8 * 66 + 4];
#pragma unroll
            for (int j = 0; j < 4; j++) {
                ahi[mt][j] = f2tf32(av[j]);
                alo[mt][j] = f2tf32(av[j] - __uint_as_float(ahi[mt][j]));
            }
        }

        const float* qb = Q_s + buf * 8192 + ((size_t)w * 64 + gid) * 8 + tg;
#pragma unroll
        for (int nt = 0; nt < 8; nt++) {
            float b0f = qb[nt * 64];
            float b1f = qb[nt * 64 + 4];
            unsigned b0h = f2tf32(b0f), b0l = f2tf32(b0f - __uint_as_float(b0h));
            unsigned b1h = f2tf32(b1f), b1l = f2tf32(b1f - __uint_as_float(b1h));
#pragma unroll
            for (int mt = 0; mt < 2; mt++) {
                mma8(c[mt][nt], ahi[mt], b0h, b1h);   // hi*hi
                mma8(c[mt][nt], alo[mt], b0h, b1h);   // lo*hi
                mma8(c[mt][nt], ahi[mt], b0l, b1l);   // hi*lo
            }
        }
        buf ^= 1;
        __syncthreads();
    }

    // Scatter C fragments to the scores slab (scaled)
#pragma unroll
    for (int mt = 0; mt < 2; mt++)
#pragma unroll
        for (int nt = 0; nt < 8; nt++) {
            int r0 = mt * 16 + gid;
            int col = w * 64 + nt * 8 + tg * 2;
            S_s[r0 * SROW + col]           = c[mt][nt][0] * SCALE_;
            S_s[r0 * SROW + col + 1]       = c[mt][nt][1] * SCALE_;
            S_s[(r0 + 8) * SROW + col]     = c[mt][nt][2] * SCALE_;
            S_s[(r0 + 8) * SROW + col + 1] = c[mt][nt][3] * SCALE_;
        }
    __syncthreads();

    // Sparsemax per row (warp per row; rows w and w+16)
#pragma unroll 1
    for (int rr = w; rr < 32; rr += 16) {
        const float* row = S_s + rr * SROW;
        float z[32];
#pragma unroll
        for (int j = 0; j < 32; j++) z[j] = row[j * 32 + lane];

        float mx = z[0];
#pragma unroll
        for (int j = 1; j < 32; j++) mx = fmaxf(mx, z[j]);
#pragma unroll
        for (int o = 16; o; o >>= 1) mx = fmaxf(mx, __shfl_xor_sync(0xffffffffu, mx, o));
#pragma unroll
        for (int j = 0; j < 32; j++) z[j] -= mx;

        float s = 0.f;
#pragma unroll
        for (int j = 0; j < 32; j++) s += z[j];
#pragma unroll
        for (int o = 16; o; o >>= 1) s += __shfl_xor_sync(0xffffffffu, s, o);

        float tau = (s - 1.f) * (1.f / 1024.f);
        int cprev = 1024;
        for (int it = 0; it < 64; it++) {
            float ls = 0.f;
            int lc = 0;
#pragma unroll
            for (int j = 0; j < 32; j++)
                if (z[j] > tau) { ls += z[j]; lc++; }
#pragma unroll
            for (int o = 16; o; o >>= 1) {
                ls += __shfl_xor_sync(0xffffffffu, ls, o);
                lc += __shfl_xor_sync(0xffffffffu, lc, o);
            }
            tau = (ls - 1.f) / (float)lc;
            if (lc == cprev) break;
            cprev = lc;
        }
        if (lane == 0) tau_s[rr] = mx + tau;   // threshold in unshifted units
    }
    __syncthreads();

    // Transposed coalesced write: out[b, n, h*1024 + m0 + lane]
    const int b = bh >> 3, h = bh & 7;
    const size_t outbase = (size_t)b * ((size_t)N_ * 8192) + (size_t)h * 1024 + m0;
    const float taum = tau_s[lane];
#pragma unroll 4
    for (int jj = 0; jj < 64; jj++) {
        int n = w + jj * 16;
        float v = S_s[lane * SROW + n] - taum;
        out[outbase + (size_t)n * 8192 + lane] = fmaxf(v, 0.f);
    }
}

// ---------------------------------------------------------------------------
extern "C" void kernel_launch(void* const* d_in, const int* in_sizes, int n_in,
                              void* d_out, int out_size) {
    (void)in_sizes; (void)n_in; (void)out_size;
    const float* x   = (const float*)d_in[0];
    const float* qw  = (const float*)d_in[1];
    const float* kw  = (const float*)d_in[2];
    const float* bnw = (const float*)d_in[3];
    const float* bnb = (const float*)d_in[4];
    float* out = (float*)d_out;

    cudaFuncSetAttribute(fused_scores_sparsemax,
                         cudaFuncAttributeMaxDynamicSharedMemorySize, FUSED_SMEM_BYTES);

    dim3 g1(4, 64, 2);
    gemm_qk_kernel<<<g1, 256>>>(x, qw, kw);
    bn_partial_kernel<<<1024, 256>>>();
    bn_finalize_kernel<<<1, 32>>>();
    normalize_kernel<<<16384, 256>>>(bnw, bnb);
    dim3 g2(32, 64);                         // m-tiles, b*h
    fused_scores_sparsemax<<<g2, 512, FUSED_SMEM_BYTES>>>(out);
}

// round 5
// speedup vs baseline: 1.4457x; 1.4457x over previous
#include <cuda_runtime.h>
#include <cuda_bf16.h>
#include <cstdint>

// Problem constants
#define B_  8
#define N_  1024
#define C_  256
#define H_  8
#define HD_ 64
#define BH_ (B_ * H_)            // 64
#define HEAD_ELEMS_ 524288       // B*N*HD per head
#define SCALE_ 0.0625f           // 1/sqrt(256)

// Scratch (device globals: allocation-free rule)
__device__ float g_q[BH_ * N_ * HD_];        // [b,h,n,d] raw projections (fp32)
__device__ float g_k[BH_ * N_ * HD_];
__device__ float g_part[1024 * 2];
__device__ float g_stats[16 * 2];
__device__ __nv_bfloat16 g_qh[BH_ * N_ * HD_];   // normalized Q hi / lo (bf16 split)
__device__ __nv_bfloat16 g_ql[BH_ * N_ * HD_];
__device__ __nv_bfloat16 g_kh[BH_ * N_ * HD_];
__device__ __nv_bfloat16 g_kl[BH_ * N_ * HD_];
__device__ float g_scores[(size_t)BH_ * N_ * N_]; // S^T[b,h,m,n] 256 MB

// ---------------------------------------------------------------------------
// Kernel 1: q = x @ qw^T, k = x @ kw^T  (fp32 FFMA)
// ---------------------------------------------------------------------------
__global__ void __launch_bounds__(256) gemm_qk_kernel(const float* __restrict__ x,
                                                      const float* __restrict__ qw,
                                                      const float* __restrict__ kw) {
    __shared__ float As[16][132];
    __shared__ float Bs[16][132];
    const int tid = threadIdx.x;
    const float* wptr = blockIdx.z ? kw : qw;
    float* outp = blockIdx.z ? g_k : g_q;
    const int m0 = blockIdx.y * 128;
    const int n0 = blockIdx.x * 128;
    const int tx = tid & 15, ty = tid >> 4;

    float acc[8][8];
#pragma unroll
    for (int i = 0; i < 8; i++)
#pragma unroll
        for (int j = 0; j < 8; j++) acc[i][j] = 0.f;

    for (int kt = 0; kt < C_; kt += 16) {
#pragma unroll
        for (int i = 0; i < 2; i++) {
            int idx = tid + i * 256;
            int r = idx >> 2;
            int kq = idx & 3;
            float4 va = *(const float4*)(x + (size_t)(m0 + r) * C_ + kt + kq * 4);
            As[kq * 4 + 0][r] = va.x; As[kq * 4 + 1][r] = va.y;
            As[kq * 4 + 2][r] = va.z; As[kq * 4 + 3][r] = va.w;
            float4 vb = *(const float4*)(wptr + (size_t)(n0 + r) * C_ + kt + kq * 4);
            Bs[kq * 4 + 0][r] = vb.x; Bs[kq * 4 + 1][r] = vb.y;
            Bs[kq * 4 + 2][r] = vb.z; Bs[kq * 4 + 3][r] = vb.w;
        }
        __syncthreads();
#pragma unroll
        for (int kk = 0; kk < 16; kk++) {
            float a[8], bv[8];
            *(float4*)(a)     = *(const float4*)&As[kk][ty * 8];
            *(float4*)(a + 4) = *(const float4*)&As[kk][ty * 8 + 4];
            *(float4*)(bv)     = *(const float4*)&Bs[kk][tx * 8];
            *(float4*)(bv + 4) = *(const float4*)&Bs[kk][tx * 8 + 4];
#pragma unroll
            for (int i = 0; i < 8; i++)
#pragma unroll
                for (int j = 0; j < 8; j++) acc[i][j] = fmaf(a[i], bv[j], acc[i][j]);
        }
        __syncthreads();
    }
    const int col0 = n0 + tx * 8;
    const int h = col0 >> 6;
    const int d0 = col0 & 63;
#pragma unroll
    for (int i = 0; i < 8; i++) {
        int row = m0 + ty * 8 + i;
        int bb = row >> 10, nn = row & 1023;
        float* dst = outp + ((size_t)(bb * H_ + h) << 16) + nn * 64 + d0;
        *(float4*)dst       = make_float4(acc[i][0], acc[i][1], acc[i][2], acc[i][3]);
        *(float4*)(dst + 4) = make_float4(acc[i][4], acc[i][5], acc[i][6], acc[i][7]);
    }
}

// ---------------------------------------------------------------------------
// Kernel 2: BN partial stats + finalize
// ---------------------------------------------------------------------------
__global__ void __launch_bounds__(256) bn_partial_kernel() {
    int bid = blockIdx.x;
    int t = bid >> 9;
    int rest = bid & 511;
    int h = rest >> 6;
    int s = rest & 63;
    int b = s >> 3, chunk = s & 7;
    const float* p = (t ? g_k : g_q) + (size_t)(b * H_ + h) * 65536 + chunk * 8192;
    const float4* p4 = (const float4*)p;
    int tid = threadIdx.x;
    float s1 = 0.f, s2 = 0.f;
#pragma unroll
    for (int j = 0; j < 8; j++) {
        float4 v = p4[tid + j * 256];
        s1 += v.x + v.y + v.z + v.w;
        s2 += v.x * v.x + v.y * v.y + v.z * v.z + v.w * v.w;
    }
#pragma unroll
    for (int o = 16; o; o >>= 1) {
        s1 += __shfl_xor_sync(0xffffffffu, s1, o);
        s2 += __shfl_xor_sync(0xffffffffu, s2, o);
    }
    __shared__ float red[16];
    if ((tid & 31) == 0) { red[(tid >> 5) * 2] = s1; red[(tid >> 5) * 2 + 1] = s2; }
    __syncthreads();
    if (tid == 0) {
        float a = 0.f, c = 0.f;
        for (int wq = 0; wq < 8; wq++) { a += red[wq * 2]; c += red[wq * 2 + 1]; }
        g_part[bid * 2] = a;
        g_part[bid * 2 + 1] = c;
    }
}

__global__ void bn_finalize_kernel() {
    int tid = threadIdx.x;
    if (tid < 16) {
        int t = tid >> 3, h = tid & 7;
        int base = t * 512 + h * 64;
        float s1 = 0.f, s2 = 0.f;
        for (int s = 0; s < 64; s++) {
            s1 += g_part[(base + s) * 2];
            s2 += g_part[(base + s) * 2 + 1];
        }
        float mean = s1 * (1.f / (float)HEAD_ELEMS_);
        float var = s2 * (1.f / (float)HEAD_ELEMS_) - mean * mean;
        g_stats[tid * 2] = mean;
        g_stats[tid * 2 + 1] = rsqrtf(var + 1e-5f);
    }
}

// ---------------------------------------------------------------------------
// Kernel 3: BN + L2 normalize; emit bf16 hi/lo split.
// ---------------------------------------------------------------------------
__global__ void __launch_bounds__(256) normalize_kernel(const float* __restrict__ bnw,
                                                        const float* __restrict__ bnb) {
    int gw = (blockIdx.x * blockDim.x + threadIdx.x) >> 5;
    int lane = threadIdx.x & 31;
    int t = gw >> 16;
    int rem = gw & 65535;
    int h = (rem >> 10) & 7;
    const float* p = (t ? g_k : g_q) + (size_t)rem * 64;
    float mean = g_stats[(t * 8 + h) * 2];
    float rstd = g_stats[(t * 8 + h) * 2 + 1];
    float w = bnw[h], bia = bnb[h];
    float2 v = *(const float2*)(p + lane * 2);
    float x0 = (v.x - mean) * rstd * w + bia;
    float x1 = (v.y - mean) * rstd * w + bia;
    float ss = x0 * x0 + x1 * x1;
#pragma unroll
    for (int o = 16; o; o >>= 1) ss += __shfl_xor_sync(0xffffffffu, ss, o);
    float inv = 1.f / fmaxf(sqrtf(ss), 1e-12f);
    x0 *= inv; x1 *= inv;

    __nv_bfloat16 h0 = __float2bfloat16(x0);
    __nv_bfloat16 h1 = __float2bfloat16(x1);
    __nv_bfloat16 l0 = __float2bfloat16(x0 - __bfloat162float(h0));
    __nv_bfloat16 l1 = __float2bfloat16(x1 - __bfloat162float(h1));
    size_t off = (size_t)rem * 64 + lane * 2;
    __nv_bfloat162 hv; hv.x = h0; hv.y = h1;
    __nv_bfloat162 lv; lv.x = l0; lv.y = l1;
    if (t) {
        *(__nv_bfloat162*)(g_kh + off) = hv;
        *(__nv_bfloat162*)(g_kl + off) = lv;
    } else {
        *(__nv_bfloat162*)(g_qh + off) = hv;
        *(__nv_bfloat162*)(g_ql + off) = lv;
    }
}

// ---------------------------------------------------------------------------
// Kernel 4: scores GEMM via mma.sync.m16n8k16 bf16 (3-pass hi/lo split).
// Per CTA: 128x128 tile of S^T[b,h,m,n]; 8 warps each 32(m) x 64(n).
// SMEM rows = 64 bf16 data in 72-elem (144B) stride -> conflict-free ldmatrix.
// ---------------------------------------------------------------------------
__device__ __forceinline__ uint32_t smem_u32(const void* p) {
    uint32_t a;
    asm("{ .reg .u64 t; cvta.to.shared.u64 t, %1; cvt.u32.u64 %0, t; }" : "=r"(a) : "l"(p));
    return a;
}
__device__ __forceinline__ void ldsm_x4(uint32_t* r, uint32_t addr) {
    asm volatile("ldmatrix.sync.aligned.m8n8.x4.shared.b16 {%0,%1,%2,%3}, [%4];"
                 : "=r"(r[0]), "=r"(r[1]), "=r"(r[2]), "=r"(r[3]) : "r"(addr));
}
__device__ __forceinline__ void mma_bf16(float* c, const uint32_t* a, uint32_t b0, uint32_t b1) {
    asm volatile("mma.sync.aligned.m16n8k16.row.col.f32.bf16.bf16.f32 "
                 "{%0,%1,%2,%3},{%4,%5,%6,%7},{%8,%9},{%0,%1,%2,%3};"
                 : "+f"(c[0]), "+f"(c[1]), "+f"(c[2]), "+f"(c[3])
                 : "r"(a[0]), "r"(a[1]), "r"(a[2]), "r"(a[3]), "r"(b0), "r"(b1));
}

#define RS 144                   // smem row stride in bytes (72 bf16)
#define SM_A_HI 0
#define SM_A_LO (128 * RS)       // 18432
#define SM_B_HI (2 * 128 * RS)   // 36864
#define SM_B_LO (3 * 128 * RS)   // 55296
#define SM_TOTAL (4 * 128 * RS)  // 73728

__global__ void __launch_bounds__(256) gemm_scores_mma() {
    extern __shared__ char sm4[];
    const int tid = threadIdx.x;
    const int wid = tid >> 5, lane = tid & 31;
    const int bh = blockIdx.z;
    const int m0 = blockIdx.y * 128;
    const int n0 = blockIdx.x * 128;

    // Stage A (=K rows m0..m0+127) and B (=Q rows n0..n0+127), hi+lo
    {
        const size_t hb = (size_t)bh * 65536;
        const uint4* sAh = (const uint4*)(g_kh + hb + (size_t)m0 * 64);
        const uint4* sAl = (const uint4*)(g_kl + hb + (size_t)m0 * 64);
        const uint4* sBh = (const uint4*)(g_qh + hb + (size_t)n0 * 64);
        const uint4* sBl = (const uint4*)(g_ql + hb + (size_t)n0 * 64);
#pragma unroll
        for (int i = 0; i < 4; i++) {
            int idx = tid + i * 256;          // 1024 16B chunks per array
            int row = idx >> 3, c = idx & 7;
            uint32_t so = row * RS + c * 16;
            *(uint4*)(sm4 + SM_A_HI + so) = sAh[idx];
            *(uint4*)(sm4 + SM_A_LO + so) = sAl[idx];
            *(uint4*)(sm4 + SM_B_HI + so) = sBh[idx];
            *(uint4*)(sm4 + SM_B_LO + so) = sBl[idx];
        }
    }
    __syncthreads();

    const uint32_t sb = smem_u32(sm4);
    const int wm = (wid & 3) * 32;
    const int wn = (wid >> 2) * 64;
    const int l07 = lane & 7;
    const int b3 = (lane >> 3) & 1;
    const int b4 = lane >> 4;
    // A x4: lanes 0-7 rows m0-7(k lo16B), 8-15 rows m8-15, 16-23 rows m0-7(k hi16B), 24-31 rows m8-15
    const uint32_t aOff = (uint32_t)(wm + b3 * 8 + l07) * RS + b4 * 16;
    // B x4 (two n-frags): lanes 0-7 rows n0-7 (k lo), 8-15 rows n0-7 (k hi), 16-23 rows n8-15 (k lo), 24-31 rows n8-15 (k hi)
    const uint32_t bOff = (uint32_t)(wn + b4 * 8 + l07) * RS + b3 * 16;

    float acc[2][8][4];
#pragma unroll
    for (int f = 0; f < 2; f++)
#pragma unroll
        for (int g = 0; g < 8; g++)
#pragma unroll
            for (int j = 0; j < 4; j++) acc[f][g][j] = 0.f;

#pragma unroll
    for (int ks = 0; ks < 4; ks++) {
        uint32_t ah[2][4], al[2][4];
#pragma unroll
        for (int f = 0; f < 2; f++) {
            ldsm_x4(ah[f], sb + SM_A_HI + aOff + f * (16 * RS) + ks * 32);
            ldsm_x4(al[f], sb + SM_A_LO + aOff + f * (16 * RS) + ks * 32);
        }
        uint32_t bhf[4][4], blf[4][4];
#pragma unroll
        for (int p = 0; p < 4; p++) {
            ldsm_x4(bhf[p], sb + SM_B_HI + bOff + p * (16 * RS) + ks * 32);
            ldsm_x4(blf[p], sb + SM_B_LO + bOff + p * (16 * RS) + ks * 32);
        }
#pragma unroll
        for (int f = 0; f < 2; f++)
#pragma unroll
            for (int p = 0; p < 4; p++) {
                mma_bf16(acc[f][2 * p],     ah[f], bhf[p][0], bhf[p][1]);
                mma_bf16(acc[f][2 * p],     al[f], bhf[p][0], bhf[p][1]);
                mma_bf16(acc[f][2 * p],     ah[f], blf[p][0], blf[p][1]);
                mma_bf16(acc[f][2 * p + 1], ah[f], bhf[p][2], bhf[p][3]);
                mma_bf16(acc[f][2 * p + 1], al[f], bhf[p][2], bhf[p][3]);
                mma_bf16(acc[f][2 * p + 1], ah[f], blf[p][2], blf[p][3]);
            }
    }

    // Epilogue: c0,c1 at (row, col), c2,c3 at (row+8, col)
    float* Cp = g_scores + (size_t)bh * 1048576;
    const int r0 = m0 + wm + (lane >> 2);
    const int c0 = n0 + wn + (lane & 3) * 2;
#pragma unroll
    for (int f = 0; f < 2; f++)
#pragma unroll
        for (int g = 0; g < 8; g++) {
            float* d0 = Cp + (size_t)(r0 + f * 16) * 1024 + c0 + g * 8;
            *(float2*)d0 = make_float2(acc[f][g][0] * SCALE_, acc[f][g][1] * SCALE_);
            *(float2*)(d0 + 8 * 1024) = make_float2(acc[f][g][2] * SCALE_, acc[f][g][3] * SCALE_);
        }
}

// ---------------------------------------------------------------------------
// Kernel 5: sparsemax (unchanged)
// ---------------------------------------------------------------------------
__global__ void __launch_bounds__(1024) sparsemax_kernel(float* __restrict__ out) {
    __shared__ float tile[128][33];
    const int bid = blockIdx.x;
    const int bh = bid >> 5;
    const int mblk = bid & 31;
    const int b = bh >> 3, h = bh & 7;
    const int w = threadIdx.x >> 5, lane = threadIdx.x & 31;
    const int m = mblk * 32 + w;
    const float* row = g_scores + (size_t)bh * 1048576 + (size_t)m * 1024;

    float z[32];
#pragma unroll
    for (int j = 0; j < 32; j++) z[j] = row[j * 32 + lane];

    float mx = z[0];
#pragma unroll
    for (int j = 1; j < 32; j++) mx = fmaxf(mx, z[j]);
#pragma unroll
    for (int o = 16; o; o >>= 1) mx = fmaxf(mx, __shfl_xor_sync(0xffffffffu, mx, o));
#pragma unroll
    for (int j = 0; j < 32; j++) z[j] -= mx;

    float s = 0.f;
#pragma unroll
    for (int j = 0; j < 32; j++) s += z[j];
#pragma unroll
    for (int o = 16; o; o >>= 1) s += __shfl_xor_sync(0xffffffffu, s, o);

    float tau = (s - 1.f) * (1.f / 1024.f);
    int cprev = 1024;
    for (int it = 0; it < 64; it++) {
        float ls = 0.f;
        int lc = 0;
#pragma unroll
        for (int j = 0; j < 32; j++)
            if (z[j] > tau) { ls += z[j]; lc++; }
#pragma unroll
        for (int o = 16; o; o >>= 1) {
            ls += __shfl_xor_sync(0xffffffffu, ls, o);
            lc += __shfl_xor_sync(0xffffffffu, lc, o);
        }
        tau = (ls - 1.f) / (float)lc;
        if (lc == cprev) break;
        cprev = lc;
    }

#pragma unroll
    for (int j = 0; j < 32; j++) z[j] = fmaxf(z[j] - tau, 0.f);

    const size_t outbase = (size_t)b * ((size_t)N_ * 8192) + (size_t)h * 1024 + mblk * 32;
#pragma unroll 1
    for (int g = 0; g < 8; g++) {
#pragma unroll
        for (int q = 0; q < 4; q++) tile[q * 32 + lane][w] = z[g * 4 + q];
        __syncthreads();
#pragma unroll
        for (int k = 0; k < 4; k++) {
            int flat = threadIdx.x + k * 1024;
            int nl = flat >> 5, ml = flat & 31;
            out[outbase + (size_t)(g * 128 + nl) * 8192 + ml] = tile[nl][ml];
        }
        __syncthreads();
    }
}

// ---------------------------------------------------------------------------
extern "C" void kernel_launch(void* const* d_in, const int* in_sizes, int n_in,
                              void* d_out, int out_size) {
    (void)in_sizes; (void)n_in; (void)out_size;
    const float* x   = (const float*)d_in[0];
    const float* qw  = (const float*)d_in[1];
    const float* kw  = (const float*)d_in[2];
    const float* bnw = (const float*)d_in[3];
    const float* bnb = (const float*)d_in[4];
    float* out = (float*)d_out;

    cudaFuncSetAttribute(gemm_scores_mma,
                         cudaFuncAttributeMaxDynamicSharedMemorySize, SM_TOTAL);

    dim3 g1(4, 64, 2);
    gemm_qk_kernel<<<g1, 256>>>(x, qw, kw);
    bn_partial_kernel<<<1024, 256>>>();
    bn_finalize_kernel<<<1, 32>>>();
    normalize_kernel<<<16384, 256>>>(bnw, bnb);
    dim3 g2(8, 8, 64);                        // n-tiles, m-tiles, bh
    gemm_scores_mma<<<g2, 256, SM_TOTAL>>>();
    sparsemax_kernel<<<2048, 1024>>>(out);
}

// round 6
// speedup vs baseline: 1.7099x; 1.1827x over previous
#include <cuda_runtime.h>
#include <cuda_bf16.h>
#include <cstdint>

// Problem constants
#define B_  8
#define N_  1024
#define C_  256
#define H_  8
#define HD_ 64
#define BH_ (B_ * H_)            // 64
#define HEAD_ELEMS_ 524288       // B*N*HD per head
#define SCALE_ 0.0625f           // 1/sqrt(256)

// Scratch (device globals: allocation-free rule)
__device__ float g_q[BH_ * N_ * HD_];        // [b,h,n,d] raw projections (fp32)
__device__ float g_k[BH_ * N_ * HD_];
__device__ float g_part[1024 * 2];
__device__ float g_stats[16 * 2];
__device__ __nv_bfloat16 g_qh[BH_ * N_ * HD_];   // normalized Q hi / lo (bf16 split)
__device__ __nv_bfloat16 g_ql[BH_ * N_ * HD_];
__device__ __nv_bfloat16 g_kh[BH_ * N_ * HD_];
__device__ __nv_bfloat16 g_kl[BH_ * N_ * HD_];
__device__ __nv_bfloat16 g_xh[8192 * 256];       // x hi/lo split
__device__ __nv_bfloat16 g_xl[8192 * 256];
__device__ __nv_bfloat16 g_wh[1024 * 256];       // [qw;kw] hi/lo split
__device__ __nv_bfloat16 g_wl[1024 * 256];
__device__ float g_scores[(size_t)BH_ * N_ * N_]; // S^T[b,h,m,n] 256 MB

// ---------------------------------------------------------------------------
// MMA helpers
// ---------------------------------------------------------------------------
__device__ __forceinline__ uint32_t smem_u32(const void* p) {
    uint32_t a;
    asm("{ .reg .u64 t; cvta.to.shared.u64 t, %1; cvt.u32.u64 %0, t; }" : "=r"(a) : "l"(p));
    return a;
}
__device__ __forceinline__ void ldsm_x4(uint32_t* r, uint32_t addr) {
    asm volatile("ldmatrix.sync.aligned.m8n8.x4.shared.b16 {%0,%1,%2,%3}, [%4];"
                 : "=r"(r[0]), "=r"(r[1]), "=r"(r[2]), "=r"(r[3]) : "r"(addr));
}
__device__ __forceinline__ void mma_bf16(float* c, const uint32_t* a, uint32_t b0, uint32_t b1) {
    asm volatile("mma.sync.aligned.m16n8k16.row.col.f32.bf16.bf16.f32 "
                 "{%0,%1,%2,%3},{%4,%5,%6,%7},{%8,%9},{%0,%1,%2,%3};"
                 : "+f"(c[0]), "+f"(c[1]), "+f"(c[2]), "+f"(c[3])
                 : "r"(a[0]), "r"(a[1]), "r"(a[2]), "r"(a[3]), "r"(b0), "r"(b1));
}

#define RS 144                   // smem row stride in bytes (72 bf16)
#define SM_A_HI 0
#define SM_A_LO (128 * RS)       // 18432
#define SM_B_HI (2 * 128 * RS)   // 36864
#define SM_B_LO (3 * 128 * RS)   // 55296
#define SM_TOTAL (4 * 128 * RS)  // 73728

// ---------------------------------------------------------------------------
// Kernel 0: bf16 hi/lo split of x (2M elems) and [qw;kw] (0.5M elems)
// ---------------------------------------------------------------------------
__global__ void __launch_bounds__(256) split_inputs_kernel(const float* __restrict__ x,
                                                           const float* __restrict__ qw,
                                                           const float* __restrict__ kw) {
    int idx = (blockIdx.x * 256 + threadIdx.x) * 4;      // 4 floats/thread
    const float* src;
    __nv_bfloat16 *dh, *dl;
    int off;
    if (idx < 2097152) {                 // x
        src = x; off = idx; dh = g_xh; dl = g_xl;
    } else if (idx < 2097152 + 131072) { // qw
        src = qw; off = idx - 2097152; dh = g_wh; dl = g_wl;
    } else {                             // kw
        src = kw; off = idx - 2097152 - 131072; dh = g_wh + 131072; dl = g_wl + 131072;
    }
    float4 v = *(const float4*)(src + off);
    __nv_bfloat16 h0 = __float2bfloat16(v.x), h1 = __float2bfloat16(v.y);
    __nv_bfloat16 h2 = __float2bfloat16(v.z), h3 = __float2bfloat16(v.w);
    __nv_bfloat162 hv0, hv1, lv0, lv1;
    hv0.x = h0; hv0.y = h1; hv1.x = h2; hv1.y = h3;
    lv0.x = __float2bfloat16(v.x - __bfloat162float(h0));
    lv0.y = __float2bfloat16(v.y - __bfloat162float(h1));
    lv1.x = __float2bfloat16(v.z - __bfloat162float(h2));
    lv1.y = __float2bfloat16(v.w - __bfloat162float(h3));
    *(__nv_bfloat162*)(dh + off)     = hv0;
    *(__nv_bfloat162*)(dh + off + 2) = hv1;
    *(__nv_bfloat162*)(dl + off)     = lv0;
    *(__nv_bfloat162*)(dl + off + 2) = lv1;
}

// ---------------------------------------------------------------------------
// Kernel 1: q/k = x @ w^T via mma.sync bf16 3-pass split. K=256 in 4 chunks.
// Per CTA: 128(m) x 128(n) tile; 8 warps of 32x64. Writes [b,h,n,d] fp32.
// ---------------------------------------------------------------------------
__global__ void __launch_bounds__(256) gemm_qk_mma(int zsel) {
    extern __shared__ char sm1[];
    const int tid = threadIdx.x;
    const int wid = tid >> 5, lane = tid & 31;
    const int zq = blockIdx.z;
    const int m0 = blockIdx.y * 128;
    const int n0 = blockIdx.x * 128;
    (void)zsel;

    const uint32_t sb = smem_u32(sm1);
    const int wm = (wid & 3) * 32;
    const int wn = (wid >> 2) * 64;
    const int l07 = lane & 7;
    const int b3 = (lane >> 3) & 1;
    const int b4 = lane >> 4;
    const uint32_t aOff = (uint32_t)(wm + b3 * 8 + l07) * RS + b4 * 16;
    const uint32_t bOff = (uint32_t)(wn + b4 * 8 + l07) * RS + b3 * 16;

    float acc[2][8][4];
#pragma unroll
    for (int f = 0; f < 2; f++)
#pragma unroll
        for (int g = 0; g < 8; g++)
#pragma unroll
            for (int j = 0; j < 4; j++) acc[f][g][j] = 0.f;

#pragma unroll 1
    for (int kc = 0; kc < 4; kc++) {
        __syncthreads();
        // stage A rows (x, m0..m0+127) and B rows (w, zq*512+n0 ..+127), cols kc*64..+64
        {
            const __nv_bfloat16* Asrc = g_xh;  // hi
            const __nv_bfloat16* Alsrc = g_xl;
            const __nv_bfloat16* Bsrc = g_wh + (size_t)(zq * 512) * 256;
            const __nv_bfloat16* Blsrc = g_wl + (size_t)(zq * 512) * 256;
#pragma unroll
            for (int i = 0; i < 4; i++) {
                int idx = tid + i * 256;          // 1024 16B chunks per array
                int row = idx >> 3, c = idx & 7;
                uint32_t so = row * RS + c * 16;
                size_t goA = (size_t)(m0 + row) * 256 + kc * 64 + c * 8;
                size_t goB = (size_t)(n0 + row) * 256 + kc * 64 + c * 8;
                *(uint4*)(sm1 + SM_A_HI + so) = *(const uint4*)(Asrc + goA);
                *(uint4*)(sm1 + SM_A_LO + so) = *(const uint4*)(Alsrc + goA);
                *(uint4*)(sm1 + SM_B_HI + so) = *(const uint4*)(Bsrc + goB);
                *(uint4*)(sm1 + SM_B_LO + so) = *(const uint4*)(Blsrc + goB);
            }
        }
        __syncthreads();

#pragma unroll
        for (int ks = 0; ks < 4; ks++) {
            uint32_t ah[2][4], al[2][4];
#pragma unroll
            for (int f = 0; f < 2; f++) {
                ldsm_x4(ah[f], sb + SM_A_HI + aOff + f * (16 * RS) + ks * 32);
                ldsm_x4(al[f], sb + SM_A_LO + aOff + f * (16 * RS) + ks * 32);
            }
            uint32_t bhf[4][4], blf[4][4];
#pragma unroll
            for (int p = 0; p < 4; p++) {
                ldsm_x4(bhf[p], sb + SM_B_HI + bOff + p * (16 * RS) + ks * 32);
                ldsm_x4(blf[p], sb + SM_B_LO + bOff + p * (16 * RS) + ks * 32);
            }
#pragma unroll
            for (int f = 0; f < 2; f++)
#pragma unroll
                for (int p = 0; p < 4; p++) {
                    mma_bf16(acc[f][2 * p],     ah[f], bhf[p][0], bhf[p][1]);
                    mma_bf16(acc[f][2 * p],     al[f], bhf[p][0], bhf[p][1]);
                    mma_bf16(acc[f][2 * p],     ah[f], blf[p][0], blf[p][1]);
                    mma_bf16(acc[f][2 * p + 1], ah[f], bhf[p][2], bhf[p][3]);
                    mma_bf16(acc[f][2 * p + 1], al[f], bhf[p][2], bhf[p][3]);
                    mma_bf16(acc[f][2 * p + 1], ah[f], blf[p][2], blf[p][3]);
                }
        }
    }

    // Epilogue -> [b,h,n_token,d] fp32
    float* outp = zq ? g_k : g_q;
    const int r0 = m0 + wm + (lane >> 2);
    const int c0 = n0 + wn + (lane & 3) * 2;
#pragma unroll
    for (int f = 0; f < 2; f++)
#pragma unroll
        for (int g = 0; g < 8; g++) {
            int col = c0 + g * 8;
            int h = col >> 6, d = col & 63;
#pragma unroll
            for (int u = 0; u < 2; u++) {
                int row = r0 + f * 16 + u * 8;
                int bb = row >> 10, nn = row & 1023;
                float* dst = outp + ((size_t)(bb * H_ + h) << 16) + nn * 64 + d;
                *(float2*)dst = make_float2(acc[f][g][u * 2], acc[f][g][u * 2 + 1]);
            }
        }
}

// ---------------------------------------------------------------------------
// Kernel 2: BN partial stats + finalize
// ---------------------------------------------------------------------------
__global__ void __launch_bounds__(256) bn_partial_kernel() {
    int bid = blockIdx.x;
    int t = bid >> 9;
    int rest = bid & 511;
    int h = rest >> 6;
    int s = rest & 63;
    int b = s >> 3, chunk = s & 7;
    const float* p = (t ? g_k : g_q) + (size_t)(b * H_ + h) * 65536 + chunk * 8192;
    const float4* p4 = (const float4*)p;
    int tid = threadIdx.x;
    float s1 = 0.f, s2 = 0.f;
#pragma unroll
    for (int j = 0; j < 8; j++) {
        float4 v = p4[tid + j * 256];
        s1 += v.x + v.y + v.z + v.w;
        s2 += v.x * v.x + v.y * v.y + v.z * v.z + v.w * v.w;
    }
#pragma unroll
    for (int o = 16; o; o >>= 1) {
        s1 += __shfl_xor_sync(0xffffffffu, s1, o);
        s2 += __shfl_xor_sync(0xffffffffu, s2, o);
    }
    __shared__ float red[16];
    if ((tid & 31) == 0) { red[(tid >> 5) * 2] = s1; red[(tid >> 5) * 2 + 1] = s2; }
    __syncthreads();
    if (tid == 0) {
        float a = 0.f, c = 0.f;
        for (int wq = 0; wq < 8; wq++) { a += red[wq * 2]; c += red[wq * 2 + 1]; }
        g_part[bid * 2] = a;
        g_part[bid * 2 + 1] = c;
    }
}

__global__ void bn_finalize_kernel() {
    int tid = threadIdx.x;
    if (tid < 16) {
        int t = tid >> 3, h = tid & 7;
        int base = t * 512 + h * 64;
        float s1 = 0.f, s2 = 0.f;
        for (int s = 0; s < 64; s++) {
            s1 += g_part[(base + s) * 2];
            s2 += g_part[(base + s) * 2 + 1];
        }
        float mean = s1 * (1.f / (float)HEAD_ELEMS_);
        float var = s2 * (1.f / (float)HEAD_ELEMS_) - mean * mean;
        g_stats[tid * 2] = mean;
        g_stats[tid * 2 + 1] = rsqrtf(var + 1e-5f);
    }
}

// ---------------------------------------------------------------------------
// Kernel 3: BN + L2 normalize; emit bf16 hi/lo split.
// ---------------------------------------------------------------------------
__global__ void __launch_bounds__(256) normalize_kernel(const float* __restrict__ bnw,
                                                        const float* __restrict__ bnb) {
    int gw = (blockIdx.x * blockDim.x + threadIdx.x) >> 5;
    int lane = threadIdx.x & 31;
    int t = gw >> 16;
    int rem = gw & 65535;
    int h = (rem >> 10) & 7;
    const float* p = (t ? g_k : g_q) + (size_t)rem * 64;
    float mean = g_stats[(t * 8 + h) * 2];
    float rstd = g_stats[(t * 8 + h) * 2 + 1];
    float w = bnw[h], bia = bnb[h];
    float2 v = *(const float2*)(p + lane * 2);
    float x0 = (v.x - mean) * rstd * w + bia;
    float x1 = (v.y - mean) * rstd * w + bia;
    float ss = x0 * x0 + x1 * x1;
#pragma unroll
    for (int o = 16; o; o >>= 1) ss += __shfl_xor_sync(0xffffffffu, ss, o);
    float inv = 1.f / fmaxf(sqrtf(ss), 1e-12f);
    x0 *= inv; x1 *= inv;

    __nv_bfloat16 h0 = __float2bfloat16(x0);
    __nv_bfloat16 h1 = __float2bfloat16(x1);
    __nv_bfloat16 l0 = __float2bfloat16(x0 - __bfloat162float(h0));
    __nv_bfloat16 l1 = __float2bfloat16(x1 - __bfloat162float(h1));
    size_t off = (size_t)rem * 64 + lane * 2;
    __nv_bfloat162 hv; hv.x = h0; hv.y = h1;
    __nv_bfloat162 lv; lv.x = l0; lv.y = l1;
    if (t) {
        *(__nv_bfloat162*)(g_kh + off) = hv;
        *(__nv_bfloat162*)(g_kl + off) = lv;
    } else {
        *(__nv_bfloat162*)(g_qh + off) = hv;
        *(__nv_bfloat162*)(g_ql + off) = lv;
    }
}

// ---------------------------------------------------------------------------
// Kernel 4: scores GEMM via mma.sync bf16 (3-pass hi/lo split) — as R5.
// ---------------------------------------------------------------------------
__global__ void __launch_bounds__(256) gemm_scores_mma() {
    extern __shared__ char sm4[];
    const int tid = threadIdx.x;
    const int wid = tid >> 5, lane = tid & 31;
    const int bh = blockIdx.z;
    const int m0 = blockIdx.y * 128;
    const int n0 = blockIdx.x * 128;

    {
        const size_t hb = (size_t)bh * 65536;
        const uint4* sAh = (const uint4*)(g_kh + hb + (size_t)m0 * 64);
        const uint4* sAl = (const uint4*)(g_kl + hb + (size_t)m0 * 64);
        const uint4* sBh = (const uint4*)(g_qh + hb + (size_t)n0 * 64);
        const uint4* sBl = (const uint4*)(g_ql + hb + (size_t)n0 * 64);
#pragma unroll
        for (int i = 0; i < 4; i++) {
            int idx = tid + i * 256;
            int row = idx >> 3, c = idx & 7;
            uint32_t so = row * RS + c * 16;
            *(uint4*)(sm4 + SM_A_HI + so) = sAh[idx];
            *(uint4*)(sm4 + SM_A_LO + so) = sAl[idx];
            *(uint4*)(sm4 + SM_B_HI + so) = sBh[idx];
            *(uint4*)(sm4 + SM_B_LO + so) = sBl[idx];
        }
    }
    __syncthreads();

    const uint32_t sb = smem_u32(sm4);
    const int wm = (wid & 3) * 32;
    const int wn = (wid >> 2) * 64;
    const int l07 = lane & 7;
    const int b3 = (lane >> 3) & 1;
    const int b4 = lane >> 4;
    const uint32_t aOff = (uint32_t)(wm + b3 * 8 + l07) * RS + b4 * 16;
    const uint32_t bOff = (uint32_t)(wn + b4 * 8 + l07) * RS + b3 * 16;

    float acc[2][8][4];
#pragma unroll
    for (int f = 0; f < 2; f++)
#pragma unroll
        for (int g = 0; g < 8; g++)
#pragma unroll
            for (int j = 0; j < 4; j++) acc[f][g][j] = 0.f;

#pragma unroll
    for (int ks = 0; ks < 4; ks++) {
        uint32_t ah[2][4], al[2][4];
#pragma unroll
        for (int f = 0; f < 2; f++) {
            ldsm_x4(ah[f], sb + SM_A_HI + aOff + f * (16 * RS) + ks * 32);
            ldsm_x4(al[f], sb + SM_A_LO + aOff + f * (16 * RS) + ks * 32);
        }
        uint32_t bhf[4][4], blf[4][4];
#pragma unroll
        for (int p = 0; p < 4; p++) {
            ldsm_x4(bhf[p], sb + SM_B_HI + bOff + p * (16 * RS) + ks * 32);
            ldsm_x4(blf[p], sb + SM_B_LO + bOff + p * (16 * RS) + ks * 32);
        }
#pragma unroll
        for (int f = 0; f < 2; f++)
#pragma unroll
            for (int p = 0; p < 4; p++) {
                mma_bf16(acc[f][2 * p],     ah[f], bhf[p][0], bhf[p][1]);
                mma_bf16(acc[f][2 * p],     al[f], bhf[p][0], bhf[p][1]);
                mma_bf16(acc[f][2 * p],     ah[f], blf[p][0], blf[p][1]);
                mma_bf16(acc[f][2 * p + 1], ah[f], bhf[p][2], bhf[p][3]);
                mma_bf16(acc[f][2 * p + 1], al[f], bhf[p][2], bhf[p][3]);
                mma_bf16(acc[f][2 * p + 1], ah[f], blf[p][2], blf[p][3]);
            }
    }

    float* Cp = g_scores + (size_t)bh * 1048576;
    const int r0 = m0 + wm + (lane >> 2);
    const int c0 = n0 + wn + (lane & 3) * 2;
#pragma unroll
    for (int f = 0; f < 2; f++)
#pragma unroll
        for (int g = 0; g < 8; g++) {
            float* d0 = Cp + (size_t)(r0 + f * 16) * 1024 + c0 + g * 8;
            *(float2*)d0 = make_float2(acc[f][g][0] * SCALE_, acc[f][g][1] * SCALE_);
            *(float2*)(d0 + 8 * 1024) = make_float2(acc[f][g][2] * SCALE_, acc[f][g][3] * SCALE_);
        }
}

// ---------------------------------------------------------------------------
// Kernel 5: sparsemax (unchanged)
// ---------------------------------------------------------------------------
__global__ void __launch_bounds__(1024) sparsemax_kernel(float* __restrict__ out) {
    __shared__ float tile[128][33];
    const int bid = blockIdx.x;
    const int bh = bid >> 5;
    const int mblk = bid & 31;
    const int b = bh >> 3, h = bh & 7;
    const int w = threadIdx.x >> 5, lane = threadIdx.x & 31;
    const int m = mblk * 32 + w;
    const float* row = g_scores + (size_t)bh * 1048576 + (size_t)m * 1024;

    float z[32];
#pragma unroll
    for (int j = 0; j < 32; j++) z[j] = row[j * 32 + lane];

    float mx = z[0];
#pragma unroll
    for (int j = 1; j < 32; j++) mx = fmaxf(mx, z[j]);
#pragma unroll
    for (int o = 16; o; o >>= 1) mx = fmaxf(mx, __shfl_xor_sync(0xffffffffu, mx, o));
#pragma unroll
    for (int j = 0; j < 32; j++) z[j] -= mx;

    float s = 0.f;
#pragma unroll
    for (int j = 0; j < 32; j++) s += z[j];
#pragma unroll
    for (int o = 16; o; o >>= 1) s += __shfl_xor_sync(0xffffffffu, s, o);

    float tau = (s - 1.f) * (1.f / 1024.f);
    int cprev = 1024;
    for (int it = 0; it < 64; it++) {
        float ls = 0.f;
        int lc = 0;
#pragma unroll
        for (int j = 0; j < 32; j++)
            if (z[j] > tau) { ls += z[j]; lc++; }
#pragma unroll
        for (int o = 16; o; o >>= 1) {
            ls += __shfl_xor_sync(0xffffffffu, ls, o);
            lc += __shfl_xor_sync(0xffffffffu, lc, o);
        }
        tau = (ls - 1.f) / (float)lc;
        if (lc == cprev) break;
        cprev = lc;
    }

#pragma unroll
    for (int j = 0; j < 32; j++) z[j] = fmaxf(z[j] - tau, 0.f);

    const size_t outbase = (size_t)b * ((size_t)N_ * 8192) + (size_t)h * 1024 + mblk * 32;
#pragma unroll 1
    for (int g = 0; g < 8; g++) {
#pragma unroll
        for (int q = 0; q < 4; q++) tile[q * 32 + lane][w] = z[g * 4 + q];
        __syncthreads();
#pragma unroll
        for (int k = 0; k < 4; k++) {
            int flat = threadIdx.x + k * 1024;
            int nl = flat >> 5, ml = flat & 31;
            out[outbase + (size_t)(g * 128 + nl) * 8192 + ml] = tile[nl][ml];
        }
        __syncthreads();
    }
}

// ---------------------------------------------------------------------------
extern "C" void kernel_launch(void* const* d_in, const int* in_sizes, int n_in,
                              void* d_out, int out_size) {
    (void)in_sizes; (void)n_in; (void)out_size;
    const float* x   = (const float*)d_in[0];
    const float* qw  = (const float*)d_in[1];
    const float* kw  = (const float*)d_in[2];
    const float* bnw = (const float*)d_in[3];
    const float* bnb = (const float*)d_in[4];
    float* out = (float*)d_out;

    cudaFuncSetAttribute(gemm_qk_mma,
                         cudaFuncAttributeMaxDynamicSharedMemorySize, SM_TOTAL);
    cudaFuncSetAttribute(gemm_scores_mma,
                         cudaFuncAttributeMaxDynamicSharedMemorySize, SM_TOTAL);

    split_inputs_kernel<<<(2359296 / 4) / 256, 256>>>(x, qw, kw);
    dim3 g1(4, 64, 2);                        // n-tiles(512/128), m-tiles(8192/128), {q,k}
    gemm_qk_mma<<<g1, 256, SM_TOTAL>>>(0);
    bn_partial_kernel<<<1024, 256>>>();
    bn_finalize_kernel<<<1, 32>>>();
    normalize_kernel<<<16384, 256>>>(bnw, bnb);
    dim3 g2(8, 8, 64);                        // n-tiles, m-tiles, bh
    gemm_scores_mma<<<g2, 256, SM_TOTAL>>>();
    sparsemax_kernel<<<2048, 1024>>>(out);
}

// round 7
// speedup vs baseline: 1.7555x; 1.0266x over previous
#include <cuda_runtime.h>
#include <cuda_bf16.h>
#include <cstdint>

// Problem constants
#define B_  8
#define N_  1024
#define C_  256
#define H_  8
#define HD_ 64
#define BH_ (B_ * H_)            // 64
#define HEAD_ELEMS_ 524288       // B*N*HD per head
#define SCALE_ 0.0625f           // 1/sqrt(256)

// Scratch (device globals: allocation-free rule)
__device__ float g_q[BH_ * N_ * HD_];        // [b,h,n,d] raw projections (fp32)
__device__ float g_k[BH_ * N_ * HD_];
__device__ float g_part[1024 * 2];
__device__ float g_stats[16 * 2];
__device__ int   g_ticket;
__device__ __nv_bfloat16 g_qh[BH_ * N_ * HD_];   // normalized Q hi / lo (bf16 split)
__device__ __nv_bfloat16 g_ql[BH_ * N_ * HD_];
__device__ __nv_bfloat16 g_kh[BH_ * N_ * HD_];
__device__ __nv_bfloat16 g_kl[BH_ * N_ * HD_];
__device__ __nv_bfloat16 g_xh[8192 * 256];       // x hi/lo split
__device__ __nv_bfloat16 g_xl[8192 * 256];
__device__ __nv_bfloat16 g_wh[1024 * 256];       // [qw;kw] hi/lo split
__device__ __nv_bfloat16 g_wl[1024 * 256];

// ---------------------------------------------------------------------------
// MMA helpers
// ---------------------------------------------------------------------------
__device__ __forceinline__ uint32_t smem_u32(const void* p) {
    uint32_t a;
    asm("{ .reg .u64 t; cvta.to.shared.u64 t, %1; cvt.u32.u64 %0, t; }" : "=r"(a) : "l"(p));
    return a;
}
__device__ __forceinline__ void ldsm_x4(uint32_t* r, uint32_t addr) {
    asm volatile("ldmatrix.sync.aligned.m8n8.x4.shared.b16 {%0,%1,%2,%3}, [%4];"
                 : "=r"(r[0]), "=r"(r[1]), "=r"(r[2]), "=r"(r[3]) : "r"(addr));
}
__device__ __forceinline__ void mma_bf16(float* c, const uint32_t* a, uint32_t b0, uint32_t b1) {
    asm volatile("mma.sync.aligned.m16n8k16.row.col.f32.bf16.bf16.f32 "
                 "{%0,%1,%2,%3},{%4,%5,%6,%7},{%8,%9},{%0,%1,%2,%3};"
                 : "+f"(c[0]), "+f"(c[1]), "+f"(c[2]), "+f"(c[3])
                 : "r"(a[0]), "r"(a[1]), "r"(a[2]), "r"(a[3]), "r"(b0), "r"(b1));
}

#define RS 144                   // smem row stride in bytes (72 bf16)
#define SM_A_HI 0
#define SM_A_LO (128 * RS)
#define SM_B_HI (2 * 128 * RS)
#define SM_B_LO (3 * 128 * RS)
#define SM_TOTAL (4 * 128 * RS)  // 73728

// ---------------------------------------------------------------------------
// Kernel 0: bf16 hi/lo split of x and [qw;kw]
// ---------------------------------------------------------------------------
__global__ void __launch_bounds__(256) split_inputs_kernel(const float* __restrict__ x,
                                                           const float* __restrict__ qw,
                                                           const float* __restrict__ kw) {
    int idx = (blockIdx.x * 256 + threadIdx.x) * 4;
    const float* src;
    __nv_bfloat16 *dh, *dl;
    int off;
    if (idx < 2097152) {
        src = x; off = idx; dh = g_xh; dl = g_xl;
    } else if (idx < 2097152 + 131072) {
        src = qw; off = idx - 2097152; dh = g_wh; dl = g_wl;
    } else {
        src = kw; off = idx - 2097152 - 131072; dh = g_wh + 131072; dl = g_wl + 131072;
    }
    float4 v = *(const float4*)(src + off);
    __nv_bfloat16 h0 = __float2bfloat16(v.x), h1 = __float2bfloat16(v.y);
    __nv_bfloat16 h2 = __float2bfloat16(v.z), h3 = __float2bfloat16(v.w);
    __nv_bfloat162 hv0, hv1, lv0, lv1;
    hv0.x = h0; hv0.y = h1; hv1.x = h2; hv1.y = h3;
    lv0.x = __float2bfloat16(v.x - __bfloat162float(h0));
    lv0.y = __float2bfloat16(v.y - __bfloat162float(h1));
    lv1.x = __float2bfloat16(v.z - __bfloat162float(h2));
    lv1.y = __float2bfloat16(v.w - __bfloat162float(h3));
    *(__nv_bfloat162*)(dh + off)     = hv0;
    *(__nv_bfloat162*)(dh + off + 2) = hv1;
    *(__nv_bfloat162*)(dl + off)     = lv0;
    *(__nv_bfloat162*)(dl + off + 2) = lv1;
}

// ---------------------------------------------------------------------------
// Kernel 1: q/k = x @ w^T via mma.sync bf16 3-pass split (as R6)
// ---------------------------------------------------------------------------
__global__ void __launch_bounds__(256) gemm_qk_mma() {
    extern __shared__ char sm1[];
    const int tid = threadIdx.x;
    const int wid = tid >> 5, lane = tid & 31;
    const int zq = blockIdx.z;
    const int m0 = blockIdx.y * 128;
    const int n0 = blockIdx.x * 128;

    const uint32_t sb = smem_u32(sm1);
    const int wm = (wid & 3) * 32;
    const int wn = (wid >> 2) * 64;
    const int l07 = lane & 7;
    const int b3 = (lane >> 3) & 1;
    const int b4 = lane >> 4;
    const uint32_t aOff = (uint32_t)(wm + b3 * 8 + l07) * RS + b4 * 16;
    const uint32_t bOff = (uint32_t)(wn + b4 * 8 + l07) * RS + b3 * 16;

    float acc[2][8][4];
#pragma unroll
    for (int f = 0; f < 2; f++)
#pragma unroll
        for (int g = 0; g < 8; g++)
#pragma unroll
            for (int j = 0; j < 4; j++) acc[f][g][j] = 0.f;

#pragma unroll 1
    for (int kc = 0; kc < 4; kc++) {
        __syncthreads();
        {
            const __nv_bfloat16* Bsrc = g_wh + (size_t)(zq * 512) * 256;
            const __nv_bfloat16* Blsrc = g_wl + (size_t)(zq * 512) * 256;
#pragma unroll
            for (int i = 0; i < 4; i++) {
                int idx = tid + i * 256;
                int row = idx >> 3, c = idx & 7;
                uint32_t so = row * RS + c * 16;
                size_t goA = (size_t)(m0 + row) * 256 + kc * 64 + c * 8;
                size_t goB = (size_t)(n0 + row) * 256 + kc * 64 + c * 8;
                *(uint4*)(sm1 + SM_A_HI + so) = *(const uint4*)(g_xh + goA);
                *(uint4*)(sm1 + SM_A_LO + so) = *(const uint4*)(g_xl + goA);
                *(uint4*)(sm1 + SM_B_HI + so) = *(const uint4*)(Bsrc + goB);
                *(uint4*)(sm1 + SM_B_LO + so) = *(const uint4*)(Blsrc + goB);
            }
        }
        __syncthreads();

#pragma unroll
        for (int ks = 0; ks < 4; ks++) {
            uint32_t ah[2][4], al[2][4];
#pragma unroll
            for (int f = 0; f < 2; f++) {
                ldsm_x4(ah[f], sb + SM_A_HI + aOff + f * (16 * RS) + ks * 32);
                ldsm_x4(al[f], sb + SM_A_LO + aOff + f * (16 * RS) + ks * 32);
            }
            uint32_t bhf[4][4], blf[4][4];
#pragma unroll
            for (int p = 0; p < 4; p++) {
                ldsm_x4(bhf[p], sb + SM_B_HI + bOff + p * (16 * RS) + ks * 32);
                ldsm_x4(blf[p], sb + SM_B_LO + bOff + p * (16 * RS) + ks * 32);
            }
#pragma unroll
            for (int f = 0; f < 2; f++)
#pragma unroll
                for (int p = 0; p < 4; p++) {
                    mma_bf16(acc[f][2 * p],     ah[f], bhf[p][0], bhf[p][1]);
                    mma_bf16(acc[f][2 * p],     al[f], bhf[p][0], bhf[p][1]);
                    mma_bf16(acc[f][2 * p],     ah[f], blf[p][0], blf[p][1]);
                    mma_bf16(acc[f][2 * p + 1], ah[f], bhf[p][2], bhf[p][3]);
                    mma_bf16(acc[f][2 * p + 1], al[f], bhf[p][2], bhf[p][3]);
                    mma_bf16(acc[f][2 * p + 1], ah[f], blf[p][2], blf[p][3]);
                }
        }
    }

    float* outp = zq ? g_k : g_q;
    const int r0 = m0 + wm + (lane >> 2);
    const int c0 = n0 + wn + (lane & 3) * 2;
#pragma unroll
    for (int f = 0; f < 2; f++)
#pragma unroll
        for (int g = 0; g < 8; g++) {
            int col = c0 + g * 8;
            int h = col >> 6, d = col & 63;
#pragma unroll
            for (int u = 0; u < 2; u++) {
                int row = r0 + f * 16 + u * 8;
                int bb = row >> 10, nn = row & 1023;
                float* dst = outp + ((size_t)(bb * H_ + h) << 16) + nn * 64 + d;
                *(float2*)dst = make_float2(acc[f][g][u * 2], acc[f][g][u * 2 + 1]);
            }
        }
}

// ---------------------------------------------------------------------------
// Kernel 2: BN partial stats; last block (ticket) does finalize in-kernel.
// ---------------------------------------------------------------------------
__global__ void __launch_bounds__(256) bn_partial_kernel() {
    int bid = blockIdx.x;
    int t = bid >> 9;
    int rest = bid & 511;
    int h = rest >> 6;
    int s = rest & 63;
    int b = s >> 3, chunk = s & 7;
    const float* p = (t ? g_k : g_q) + (size_t)(b * H_ + h) * 65536 + chunk * 8192;
    const float4* p4 = (const float4*)p;
    int tid = threadIdx.x;
    float s1 = 0.f, s2 = 0.f;
#pragma unroll
    for (int j = 0; j < 8; j++) {
        float4 v = p4[tid + j * 256];
        s1 += v.x + v.y + v.z + v.w;
        s2 += v.x * v.x + v.y * v.y + v.z * v.z + v.w * v.w;
    }
#pragma unroll
    for (int o = 16; o; o >>= 1) {
        s1 += __shfl_xor_sync(0xffffffffu, s1, o);
        s2 += __shfl_xor_sync(0xffffffffu, s2, o);
    }
    __shared__ float red[16];
    __shared__ int islast;
    if ((tid & 31) == 0) { red[(tid >> 5) * 2] = s1; red[(tid >> 5) * 2 + 1] = s2; }
    __syncthreads();
    if (tid == 0) {
        float a = 0.f, c = 0.f;
        for (int wq = 0; wq < 8; wq++) { a += red[wq * 2]; c += red[wq * 2 + 1]; }
        g_part[bid * 2] = a;
        g_part[bid * 2 + 1] = c;
        __threadfence();
        islast = (atomicAdd(&g_ticket, 1) == 1023);
    }
    __syncthreads();
    if (islast) {
        __threadfence();
        if (tid < 16) {
            int tt = tid >> 3, hh = tid & 7;
            int base = tt * 512 + hh * 64;
            float a = 0.f, c = 0.f;
#pragma unroll 8
            for (int q = 0; q < 64; q++) {
                a += g_part[(base + q) * 2];
                c += g_part[(base + q) * 2 + 1];
            }
            float mean = a * (1.f / (float)HEAD_ELEMS_);
            float var = c * (1.f / (float)HEAD_ELEMS_) - mean * mean;
            g_stats[tid * 2] = mean;
            g_stats[tid * 2 + 1] = rsqrtf(var + 1e-5f);
        }
        if (tid == 0) g_ticket = 0;   // reset for graph replay
    }
}

// ---------------------------------------------------------------------------
// Kernel 3: BN + L2 normalize; emit bf16 hi/lo split.
// ---------------------------------------------------------------------------
__global__ void __launch_bounds__(256) normalize_kernel(const float* __restrict__ bnw,
                                                        const float* __restrict__ bnb) {
    int gw = (blockIdx.x * blockDim.x + threadIdx.x) >> 5;
    int lane = threadIdx.x & 31;
    int t = gw >> 16;
    int rem = gw & 65535;
    int h = (rem >> 10) & 7;
    const float* p = (t ? g_k : g_q) + (size_t)rem * 64;
    float mean = g_stats[(t * 8 + h) * 2];
    float rstd = g_stats[(t * 8 + h) * 2 + 1];
    float w = bnw[h], bia = bnb[h];
    float2 v = *(const float2*)(p + lane * 2);
    float x0 = (v.x - mean) * rstd * w + bia;
    float x1 = (v.y - mean) * rstd * w + bia;
    float ss = x0 * x0 + x1 * x1;
#pragma unroll
    for (int o = 16; o; o >>= 1) ss += __shfl_xor_sync(0xffffffffu, ss, o);
    float inv = 1.f / fmaxf(sqrtf(ss), 1e-12f);
    x0 *= inv; x1 *= inv;

    __nv_bfloat16 h0 = __float2bfloat16(x0);
    __nv_bfloat16 h1 = __float2bfloat16(x1);
    __nv_bfloat16 l0 = __float2bfloat16(x0 - __bfloat162float(h0));
    __nv_bfloat16 l1 = __float2bfloat16(x1 - __bfloat162float(h1));
    size_t off = (size_t)rem * 64 + lane * 2;
    __nv_bfloat162 hv; hv.x = h0; hv.y = h1;
    __nv_bfloat162 lv; lv.x = l0; lv.y = l1;
    if (t) {
        *(__nv_bfloat162*)(g_kh + off) = hv;
        *(__nv_bfloat162*)(g_kl + off) = lv;
    } else {
        *(__nv_bfloat162*)(g_qh + off) = hv;
        *(__nv_bfloat162*)(g_ql + off) = lv;
    }
}

// ---------------------------------------------------------------------------
// Kernel 4 (fused): per (bh, 32-row m-tile): scores slab [32 x 1024] via
// mma.sync bf16 3-pass (A=K from smem ldmatrix, B=Q fragments direct from
// global), sparsemax (Michelot) in smem, transposed coalesced output.
// Eliminates the 512MB scores round-trip entirely.
// ---------------------------------------------------------------------------
#define SROW 1025
#define FS_SLAB 0
#define FS_KHI  (32 * SROW * 4)            // 131200
#define FS_KLO  (FS_KHI + 32 * RS)         // +4608
#define FS_TAU  (FS_KLO + 32 * RS)
#define FS_SMEM (FS_TAU + 128)             // 140544 bytes

__global__ void __launch_bounds__(512, 1) fused_scores_sparsemax(float* __restrict__ out) {
    extern __shared__ char smf[];
    float* S_s = (float*)(smf + FS_SLAB);
    float* tau_s = (float*)(smf + FS_TAU);
    const uint32_t sb = smem_u32(smf);
    const int tid = threadIdx.x;
    const int w = tid >> 5, lane = tid & 31;
    const int bh = blockIdx.y;
    const int m0 = blockIdx.x * 32;
    const size_t hbase = (size_t)bh * 65536;
    const __nv_bfloat16* Qh = g_qh + hbase;
    const __nv_bfloat16* Ql = g_ql + hbase;

    // Stage K tile [32 x 64] hi+lo into smem (RS=144B rows for ldmatrix)
    {
        int half = tid >> 8;               // 0: hi, 1: lo
        int idx = tid & 255;               // 32 rows x 8 chunks
        int row = idx >> 3, c = idx & 7;
        const __nv_bfloat16* src = (half ? g_kl : g_kh) + hbase + (size_t)(m0 + row) * 64 + c * 8;
        char* dst = smf + (half ? FS_KLO : FS_KHI) + row * RS + c * 16;
        *(uint4*)dst = *(const uint4*)src;
    }
    __syncthreads();

    // GEMM: warp w computes rows m0..m0+31 x cols [w*64, w*64+64)
    const int l07 = lane & 7;
    const int b3 = (lane >> 3) & 1;
    const int b4 = lane >> 4;
    const uint32_t aOff = (uint32_t)(b3 * 8 + l07) * RS + b4 * 16;
    const int nq = lane >> 2;              // B fragment row within 8-group
    const int kq = (lane & 3) * 2;         // B fragment k offset

    float acc[2][8][4];
#pragma unroll
    for (int f = 0; f < 2; f++)
#pragma unroll
        for (int p = 0; p < 8; p++)
#pragma unroll
            for (int j = 0; j < 4; j++) acc[f][p][j] = 0.f;

#pragma unroll
    for (int ks = 0; ks < 4; ks++) {
        uint32_t ah[2][4], al[2][4];
#pragma unroll
        for (int f = 0; f < 2; f++) {
            ldsm_x4(ah[f], sb + FS_KHI + aOff + f * (16 * RS) + ks * 32);
            ldsm_x4(al[f], sb + FS_KLO + aOff + f * (16 * RS) + ks * 32);
        }
#pragma unroll
        for (int p = 0; p < 8; p++) {
            size_t go = (size_t)(w * 64 + p * 8 + nq) * 64 + ks * 16 + kq;
            uint32_t bh0 = *(const uint32_t*)(Qh + go);
            uint32_t bh1 = *(const uint32_t*)(Qh + go + 8);
            uint32_t bl0 = *(const uint32_t*)(Ql + go);
            uint32_t bl1 = *(const uint32_t*)(Ql + go + 8);
#pragma unroll
            for (int f = 0; f < 2; f++) {
                mma_bf16(acc[f][p], ah[f], bh0, bh1);
                mma_bf16(acc[f][p], al[f], bh0, bh1);
                mma_bf16(acc[f][p], ah[f], bl0, bl1);
            }
        }
    }

    // Scatter to slab (scaled); scalar stores (SROW odd -> conflict-free phases)
#pragma unroll
    for (int f = 0; f < 2; f++)
#pragma unroll
        for (int p = 0; p < 8; p++) {
            int r = f * 16 + (lane >> 2);
            int col = w * 64 + p * 8 + (lane & 3) * 2;
            S_s[r * SROW + col]           = acc[f][p][0] * SCALE_;
            S_s[r * SROW + col + 1]       = acc[f][p][1] * SCALE_;
            S_s[(r + 8) * SROW + col]     = acc[f][p][2] * SCALE_;
            S_s[(r + 8) * SROW + col + 1] = acc[f][p][3] * SCALE_;
        }
    __syncthreads();

    // Sparsemax per row: warp w handles rows w and w+16
#pragma unroll 1
    for (int rr = w; rr < 32; rr += 16) {
        const float* row = S_s + rr * SROW;
        float z[32];
#pragma unroll
        for (int j = 0; j < 32; j++) z[j] = row[j * 32 + lane];

        float mx = z[0];
#pragma unroll
        for (int j = 1; j < 32; j++) mx = fmaxf(mx, z[j]);
#pragma unroll
        for (int o = 16; o; o >>= 1) mx = fmaxf(mx, __shfl_xor_sync(0xffffffffu, mx, o));
#pragma unroll
        for (int j = 0; j < 32; j++) z[j] -= mx;

        float s = 0.f;
#pragma unroll
        for (int j = 0; j < 32; j++) s += z[j];
#pragma unroll
        for (int o = 16; o; o >>= 1) s += __shfl_xor_sync(0xffffffffu, s, o);

        float tau = (s - 1.f) * (1.f / 1024.f);
        int cprev = 1024;
        for (int it = 0; it < 64; it++) {
            float ls = 0.f;
            int lc = 0;
#pragma unroll
            for (int j = 0; j < 32; j++)
                if (z[j] > tau) { ls += z[j]; lc++; }
#pragma unroll
            for (int o = 16; o; o >>= 1) {
                ls += __shfl_xor_sync(0xffffffffu, ls, o);
                lc += __shfl_xor_sync(0xffffffffu, lc, o);
            }
            tau = (ls - 1.f) / (float)lc;
            if (lc == cprev) break;
            cprev = lc;
        }
        if (lane == 0) tau_s[rr] = mx + tau;     // threshold in raw units
    }
    __syncthreads();

    // Transposed coalesced output: out[b, n, h*1024 + m0 + lane]
    const int b = bh >> 3, h = bh & 7;
    const size_t outbase = (size_t)b * ((size_t)N_ * 8192) + (size_t)h * 1024 + m0;
    const float thr = tau_s[lane];
#pragma unroll 4
    for (int jj = 0; jj < 64; jj++) {
        int n = jj * 16 + w;
        float v = S_s[lane * SROW + n] - thr;
        out[outbase + (size_t)n * 8192 + lane] = fmaxf(v, 0.f);
    }
}

// ---------------------------------------------------------------------------
extern "C" void kernel_launch(void* const* d_in, const int* in_sizes, int n_in,
                              void* d_out, int out_size) {
    (void)in_sizes; (void)n_in; (void)out_size;
    const float* x   = (const float*)d_in[0];
    const float* qw  = (const float*)d_in[1];
    const float* kw  = (const float*)d_in[2];
    const float* bnw = (const float*)d_in[3];
    const float* bnb = (const float*)d_in[4];
    float* out = (float*)d_out;

    cudaFuncSetAttribute(gemm_qk_mma,
                         cudaFuncAttributeMaxDynamicSharedMemorySize, SM_TOTAL);
    cudaFuncSetAttribute(fused_scores_sparsemax,
                         cudaFuncAttributeMaxDynamicSharedMemorySize, FS_SMEM);

    split_inputs_kernel<<<(2359296 / 4) / 256, 256>>>(x, qw, kw);
    dim3 g1(4, 64, 2);
    gemm_qk_mma<<<g1, 256, SM_TOTAL>>>();
    bn_partial_kernel<<<1024, 256>>>();
    normalize_kernel<<<16384, 256>>>(bnw, bnb);
    dim3 g2(32, 64);                          // m-tiles, bh
    fused_scores_sparsemax<<<g2, 512, FS_SMEM>>>(out);
}

// round 10
// speedup vs baseline: 1.7650x; 1.0055x over previous
#include <cuda_runtime.h>
#include <cuda_bf16.h>
#include <cstdint>

// Problem constants
#define B_  8
#define N_  1024
#define C_  256
#define H_  8
#define BH_ (B_ * H_)
#define HEAD_ELEMS_ 524288
#define SCALE_ 0.0625f

// Scratch (device globals)
__device__ float g_q[BH_ * N_ * 64];
__device__ float g_k[BH_ * N_ * 64];
__device__ float g_part[2048];
__device__ float g_stats[16 * 2];
__device__ int   g_ticket;
__device__ __nv_bfloat16 g_qh[BH_ * N_ * 64];
__device__ __nv_bfloat16 g_ql[BH_ * N_ * 64];
__device__ __nv_bfloat16 g_kh[BH_ * N_ * 64];
__device__ __nv_bfloat16 g_kl[BH_ * N_ * 64];
__device__ __nv_bfloat16 g_xh[8192 * 256];
__device__ __nv_bfloat16 g_xl[8192 * 256];
__device__ __nv_bfloat16 g_wh[1024 * 256];
__device__ __nv_bfloat16 g_wl[1024 * 256];

// ---------------------------------------------------------------------------
// helpers
// ---------------------------------------------------------------------------
__device__ __forceinline__ uint32_t smem_u32(const void* p) {
    uint32_t a;
    asm("{ .reg .u64 t; cvta.to.shared.u64 t, %1; cvt.u32.u64 %0, t; }" : "=r"(a) : "l"(p));
    return a;
}
__device__ __forceinline__ void ldsm_x4(uint32_t* r, uint32_t addr) {
    asm volatile("ldmatrix.sync.aligned.m8n8.x4.shared.b16 {%0,%1,%2,%3}, [%4];"
                 : "=r"(r[0]), "=r"(r[1]), "=r"(r[2]), "=r"(r[3]) : "r"(addr));
}
__device__ __forceinline__ void mma_bf16(float* c, const uint32_t* a, uint32_t b0, uint32_t b1) {
    asm volatile("mma.sync.aligned.m16n8k16.row.col.f32.bf16.bf16.f32 "
                 "{%0,%1,%2,%3},{%4,%5,%6,%7},{%8,%9},{%0,%1,%2,%3};"
                 : "+f"(c[0]), "+f"(c[1]), "+f"(c[2]), "+f"(c[3])
                 : "r"(a[0]), "r"(a[1]), "r"(a[2]), "r"(a[3]), "r"(b0), "r"(b1));
}
__device__ __forceinline__ void cp16(uint32_t d, const void* s) {
    asm volatile("cp.async.cg.shared.global [%0], [%1], 16;" :: "r"(d), "l"(s));
}
#define CP_COMMIT() asm volatile("cp.async.commit_group;" ::: "memory")
#define CP_WAIT1()  asm volatile("cp.async.wait_group 1;" ::: "memory")
#define CP_WAIT0()  asm volatile("cp.async.wait_group 0;" ::: "memory")

// ---------------------------------------------------------------------------
// Kernel 0: bf16 hi/lo split of x and [qw;kw]
// ---------------------------------------------------------------------------
__global__ void __launch_bounds__(256) split_inputs_kernel(const float* __restrict__ x,
                                                           const float* __restrict__ qw,
                                                           const float* __restrict__ kw) {
    int idx = (blockIdx.x * 256 + threadIdx.x) * 4;
    const float* src;
    __nv_bfloat16 *dh, *dl;
    int off;
    if (idx < 2097152) {
        src = x; off = idx; dh = g_xh; dl = g_xl;
    } else if (idx < 2097152 + 131072) {
        src = qw; off = idx - 2097152; dh = g_wh; dl = g_wl;
    } else {
        src = kw; off = idx - 2097152 - 131072; dh = g_wh + 131072; dl = g_wl + 131072;
    }
    float4 v = *(const float4*)(src + off);
    __nv_bfloat16 h0 = __float2bfloat16(v.x), h1 = __float2bfloat16(v.y);
    __nv_bfloat16 h2 = __float2bfloat16(v.z), h3 = __float2bfloat16(v.w);
    __nv_bfloat162 hv0, hv1, lv0, lv1;
    hv0.x = h0; hv0.y = h1; hv1.x = h2; hv1.y = h3;
    lv0.x = __float2bfloat16(v.x - __bfloat162float(h0));
    lv0.y = __float2bfloat16(v.y - __bfloat162float(h1));
    lv1.x = __float2bfloat16(v.z - __bfloat162float(h2));
    lv1.y = __float2bfloat16(v.w - __bfloat162float(h3));
    *(__nv_bfloat162*)(dh + off)     = hv0;
    *(__nv_bfloat162*)(dh + off + 2) = hv1;
    *(__nv_bfloat162*)(dl + off)     = lv0;
    *(__nv_bfloat162*)(dl + off + 2) = lv1;
}

// ---------------------------------------------------------------------------
// Kernel 1: q/k = x @ w^T, cp.async 2-stage pipeline over 8 k-chunks of 32.
// 80B smem rows (conflict-free ldmatrix). Epilogue folds BN partial stats;
// last CTA (ticket) finalizes g_stats. No spin-waits (cannot hang).
// ---------------------------------------------------------------------------
#define QK_STAGE 40960
#define QK_AHI 0
#define QK_ALO 10240
#define QK_BHI 20480
#define QK_BLO 30720
#define QK_SMEM (2 * QK_STAGE)   // 81920

__global__ void __launch_bounds__(256, 2) gemm_qk_mma() {
    extern __shared__ char smq[];
    const uint32_t sb = smem_u32(smq);
    const int tid = threadIdx.x;
    const int wid = tid >> 5, lane = tid & 31;
    const int bx = blockIdx.x, by = blockIdx.y, bz = blockIdx.z;
    const int m0 = by * 128, n0 = bx * 128;
    const __nv_bfloat16* Bh = g_wh + (size_t)(bz * 512) * 256;
    const __nv_bfloat16* Bl = g_wl + (size_t)(bz * 512) * 256;

    auto stage = [&](int kc, int buf) {
        uint32_t base = sb + buf * QK_STAGE;
#pragma unroll
        for (int i = 0; i < 2; i++) {
            int idx = tid + i * 256;           // 512 chunks of 16B per array
            int row = idx >> 2, c = idx & 3;
            uint32_t so = (uint32_t)row * 80 + c * 16;
            size_t goA = (size_t)(m0 + row) * 256 + kc * 32 + c * 8;
            size_t goB = (size_t)(n0 + row) * 256 + kc * 32 + c * 8;
            cp16(base + QK_AHI + so, g_xh + goA);
            cp16(base + QK_ALO + so, g_xl + goA);
            cp16(base + QK_BHI + so, Bh + goB);
            cp16(base + QK_BLO + so, Bl + goB);
        }
    };

    const int wm = (wid & 3) * 32;
    const int wn = (wid >> 2) * 64;
    const int l07 = lane & 7;
    const int b3 = (lane >> 3) & 1;
    const int b4 = lane >> 4;
    const uint32_t aOff = (uint32_t)(wm + b3 * 8 + l07) * 80 + b4 * 16;
    const uint32_t bOff = (uint32_t)(wn + b4 * 8 + l07) * 80 + b3 * 16;

    float acc[2][8][4];
#pragma unroll
    for (int f = 0; f < 2; f++)
#pragma unroll
        for (int g = 0; g < 8; g++)
#pragma unroll
            for (int j = 0; j < 4; j++) acc[f][g][j] = 0.f;

    stage(0, 0);
    CP_COMMIT();

#pragma unroll 1
    for (int kc = 0; kc < 8; kc++) {
        if (kc < 7) { stage(kc + 1, (kc + 1) & 1); CP_COMMIT(); CP_WAIT1(); }
        else CP_WAIT0();
        __syncthreads();
        uint32_t base = sb + (kc & 1) * QK_STAGE;
#pragma unroll
        for (int ks = 0; ks < 2; ks++) {
            uint32_t ah[2][4], al[2][4];
#pragma unroll
            for (int f = 0; f < 2; f++) {
                ldsm_x4(ah[f], base + QK_AHI + aOff + f * 1280 + ks * 32);
                ldsm_x4(al[f], base + QK_ALO + aOff + f * 1280 + ks * 32);
            }
            uint32_t bhf[4][4], blf[4][4];
#pragma unroll
            for (int p = 0; p < 4; p++) {
                ldsm_x4(bhf[p], base + QK_BHI + bOff + p * 1280 + ks * 32);
                ldsm_x4(blf[p], base + QK_BLO + bOff + p * 1280 + ks * 32);
            }
#pragma unroll
            for (int f = 0; f < 2; f++)
#pragma unroll
                for (int p = 0; p < 4; p++) {
                    mma_bf16(acc[f][2 * p],     ah[f], bhf[p][0], bhf[p][1]);
                    mma_bf16(acc[f][2 * p],     al[f], bhf[p][0], bhf[p][1]);
                    mma_bf16(acc[f][2 * p],     ah[f], blf[p][0], blf[p][1]);
                    mma_bf16(acc[f][2 * p + 1], ah[f], bhf[p][2], bhf[p][3]);
                    mma_bf16(acc[f][2 * p + 1], al[f], bhf[p][2], bhf[p][3]);
                    mma_bf16(acc[f][2 * p + 1], ah[f], blf[p][2], blf[p][3]);
                }
        }
        __syncthreads();
    }

    // Epilogue: write q/k [b,h,n,d] fp32 + BN partial stats
    float* outp = bz ? g_k : g_q;
    const int r0 = m0 + wm + (lane >> 2);
    const int c0 = n0 + wn + (lane & 3) * 2;
    float s1 = 0.f, s2 = 0.f;
#pragma unroll
    for (int f = 0; f < 2; f++)
#pragma unroll
        for (int g = 0; g < 8; g++) {
            int col = c0 + g * 8;
            int h = col >> 6, d = col & 63;
#pragma unroll
            for (int u = 0; u < 2; u++) {
                float v0 = acc[f][g][u * 2], v1 = acc[f][g][u * 2 + 1];
                s1 += v0 + v1;
                s2 += v0 * v0 + v1 * v1;
                int row = r0 + f * 16 + u * 8;
                int bb = row >> 10, nn = row & 1023;
                float* dst = outp + ((size_t)(bb * H_ + h) << 16) + nn * 64 + d;
                *(float2*)dst = make_float2(v0, v1);
            }
        }
#pragma unroll
    for (int o = 16; o; o >>= 1) {
        s1 += __shfl_xor_sync(0xffffffffu, s1, o);
        s2 += __shfl_xor_sync(0xffffffffu, s2, o);
    }
    __shared__ float wsum[8], wsq[8];
    __shared__ int islast;
    if (lane == 0) { wsum[wid] = s1; wsq[wid] = s2; }
    __syncthreads();
    if (tid == 0) {
        int slot = ((bz * 4 + bx) * 64 + by) * 4;
        g_part[slot + 0] = wsum[0] + wsum[1] + wsum[2] + wsum[3];
        g_part[slot + 1] = wsq[0] + wsq[1] + wsq[2] + wsq[3];
        g_part[slot + 2] = wsum[4] + wsum[5] + wsum[6] + wsum[7];
        g_part[slot + 3] = wsq[4] + wsq[5] + wsq[6] + wsq[7];
        __threadfence();
        islast = (atomicAdd(&g_ticket, 1) == 511);
    }
    __syncthreads();
    if (islast) {
        __threadfence();
        if (tid < 16) {
            int t = tid >> 3, h = tid & 7;
            int bx2 = h >> 1, sel = h & 1;
            float a = 0.f, c2 = 0.f;
            for (int by2 = 0; by2 < 64; by2++) {
                int slot = ((t * 4 + bx2) * 64 + by2) * 4 + sel * 2;
                a += g_part[slot];
                c2 += g_part[slot + 1];
            }
            float mean = a * (1.f / (float)HEAD_ELEMS_);
            float var = c2 * (1.f / (float)HEAD_ELEMS_) - mean * mean;
            g_stats[tid * 2] = mean;
            g_stats[tid * 2 + 1] = rsqrtf(var + 1e-5f);
        }
        if (tid == 0) g_ticket = 0;   // reset for graph replay
    }
}

// ---------------------------------------------------------------------------
// Kernel 2: BN + L2 normalize; emit bf16 hi/lo split.
// ---------------------------------------------------------------------------
__global__ void __launch_bounds__(256) normalize_kernel(const float* __restrict__ bnw,
                                                        const float* __restrict__ bnb) {
    int gw = (blockIdx.x * blockDim.x + threadIdx.x) >> 5;
    int lane = threadIdx.x & 31;
    int t = gw >> 16;
    int rem = gw & 65535;
    int h = (rem >> 10) & 7;
    const float* p = (t ? g_k : g_q) + (size_t)rem * 64;
    float mean = g_stats[(t * 8 + h) * 2];
    float rstd = g_stats[(t * 8 + h) * 2 + 1];
    float w = bnw[h], bia = bnb[h];
    float2 v = *(const float2*)(p + lane * 2);
    float x0 = (v.x - mean) * rstd * w + bia;
    float x1 = (v.y - mean) * rstd * w + bia;
    float ss = x0 * x0 + x1 * x1;
#pragma unroll
    for (int o = 16; o; o >>= 1) ss += __shfl_xor_sync(0xffffffffu, ss, o);
    float inv = 1.f / fmaxf(sqrtf(ss), 1e-12f);
    x0 *= inv; x1 *= inv;

    __nv_bfloat16 h0 = __float2bfloat16(x0);
    __nv_bfloat16 h1 = __float2bfloat16(x1);
    __nv_bfloat16 l0 = __float2bfloat16(x0 - __bfloat162float(h0));
    __nv_bfloat16 l1 = __float2bfloat16(x1 - __bfloat162float(h1));
    size_t off = (size_t)rem * 64 + lane * 2;
    __nv_bfloat162 hv; hv.x = h0; hv.y = h1;
    __nv_bfloat162 lv; lv.x = l0; lv.y = l1;
    if (t) {
        *(__nv_bfloat162*)(g_kh + off) = hv;
        *(__nv_bfloat162*)(g_kl + off) = lv;
    } else {
        *(__nv_bfloat162*)(g_qh + off) = hv;
        *(__nv_bfloat162*)(g_ql + off) = lv;
    }
}

// ---------------------------------------------------------------------------
// Kernel 3 (fused, R7-proven): scores slab [32 x 1024] per CTA via mma.sync
// (A=K smem ldmatrix, B=Q frags direct from global), sparsemax in-slab,
// transposed coalesced output.
// ---------------------------------------------------------------------------
#define SROW 1025
#define FS_SLAB 0
#define FS_KHI  (32 * SROW * 4)            // 131200
#define FS_KLO  (FS_KHI + 32 * 144)        // +4608
#define FS_TAU  (FS_KLO + 32 * 144)
#define FS_SMEM (FS_TAU + 128)             // 140544 bytes

__global__ void __launch_bounds__(512, 1) fused_scores_sparsemax(float* __restrict__ out) {
    extern __shared__ char smf[];
    float* S_s = (float*)(smf + FS_SLAB);
    float* tau_s = (float*)(smf + FS_TAU);
    const uint32_t sb = smem_u32(smf);
    const int tid = threadIdx.x;
    const int w = tid >> 5, lane = tid & 31;
    const int bh = blockIdx.y;
    const int m0 = blockIdx.x * 32;
    const size_t hbase = (size_t)bh * 65536;
    const __nv_bfloat16* Qh = g_qh + hbase;
    const __nv_bfloat16* Ql = g_ql + hbase;

    // Stage K tile [32 x 64] hi+lo into smem (144B rows for ldmatrix)
    {
        int half = tid >> 8;               // 0: hi, 1: lo
        int idx = tid & 255;               // 32 rows x 8 chunks
        int row = idx >> 3, c = idx & 7;
        const __nv_bfloat16* src = (half ? g_kl : g_kh) + hbase + (size_t)(m0 + row) * 64 + c * 8;
        char* dst = smf + (half ? FS_KLO : FS_KHI) + row * 144 + c * 16;
        *(uint4*)dst = *(const uint4*)src;
    }
    __syncthreads();

    // GEMM: warp w computes rows m0..m0+31 x cols [w*64, w*64+64)
    const int l07 = lane & 7;
    const int b3 = (lane >> 3) & 1;
    const int b4 = lane >> 4;
    const uint32_t aOff = (uint32_t)(b3 * 8 + l07) * 144 + b4 * 16;
    const int nq = lane >> 2;
    const int kq = (lane & 3) * 2;

    float acc[2][8][4];
#pragma unroll
    for (int f = 0; f < 2; f++)
#pragma unroll
        for (int p = 0; p < 8; p++)
#pragma unroll
            for (int j = 0; j < 4; j++) acc[f][p][j] = 0.f;

#pragma unroll
    for (int ks = 0; ks < 4; ks++) {
        uint32_t ah[2][4], al[2][4];
#pragma unroll
        for (int f = 0; f < 2; f++) {
            ldsm_x4(ah[f], sb + FS_KHI + aOff + f * (16 * 144) + ks * 32);
            ldsm_x4(al[f], sb + FS_KLO + aOff + f * (16 * 144) + ks * 32);
        }
#pragma unroll
        for (int p = 0; p < 8; p++) {
            size_t go = (size_t)(w * 64 + p * 8 + nq) * 64 + ks * 16 + kq;
            uint32_t bh0 = *(const uint32_t*)(Qh + go);
            uint32_t bh1 = *(const uint32_t*)(Qh + go + 8);
            uint32_t bl0 = *(const uint32_t*)(Ql + go);
            uint32_t bl1 = *(const uint32_t*)(Ql + go + 8);
#pragma unroll
            for (int f = 0; f < 2; f++) {
                mma_bf16(acc[f][p], ah[f], bh0, bh1);
                mma_bf16(acc[f][p], al[f], bh0, bh1);
                mma_bf16(acc[f][p], ah[f], bl0, bl1);
            }
        }
    }

    // Scatter to slab (scaled)
#pragma unroll
    for (int f = 0; f < 2; f++)
#pragma unroll
        for (int p = 0; p < 8; p++) {
            int r = f * 16 + (lane >> 2);
            int col = w * 64 + p * 8 + (lane & 3) * 2;
            S_s[r * SROW + col]           = acc[f][p][0] * SCALE_;
            S_s[r * SROW + col + 1]       = acc[f][p][1] * SCALE_;
            S_s[(r + 8) * SROW + col]     = acc[f][p][2] * SCALE_;
            S_s[(r + 8) * SROW + col + 1] = acc[f][p][3] * SCALE_;
        }
    __syncthreads();

    // Sparsemax per row: warp w handles rows w and w+16
#pragma unroll 1
    for (int rr = w; rr < 32; rr += 16) {
        const float* row = S_s + rr * SROW;
        float z[32];
#pragma unroll
        for (int j = 0; j < 32; j++) z[j] = row[j * 32 + lane];

        float mx = z[0];
#pragma unroll
        for (int j = 1; j < 32; j++) mx = fmaxf(mx, z[j]);
#pragma unroll
        for (int o = 16; o; o >>= 1) mx = fmaxf(mx, __shfl_xor_sync(0xffffffffu, mx, o));
#pragma unroll
        for (int j = 0; j < 32; j++) z[j] -= mx;

        float s = 0.f;
#pragma unroll
        for (int j = 0; j < 32; j++) s += z[j];
#pragma unroll
        for (int o = 16; o; o >>= 1) s += __shfl_xor_sync(0xffffffffu, s, o);

        float tau = (s - 1.f) * (1.f / 1024.f);
        int cprev = 1024;
        for (int it = 0; it < 64; it++) {
            float ls = 0.f;
            int lc = 0;
#pragma unroll
            for (int j = 0; j < 32; j++)
                if (z[j] > tau) { ls += z[j]; lc++; }
#pragma unroll
            for (int o = 16; o; o >>= 1) {
                ls += __shfl_xor_sync(0xffffffffu, ls, o);
                lc += __shfl_xor_sync(0xffffffffu, lc, o);
            }
            tau = (ls - 1.f) / (float)lc;
            if (lc == cprev) break;
            cprev = lc;
        }
        if (lane == 0) tau_s[rr] = mx + tau;
    }
    __syncthreads();

    // Transposed coalesced output: out[b, n, h*1024 + m0 + lane]
    const int b = bh >> 3, h = bh & 7;
    const size_t outbase = (size_t)b * ((size_t)N_ * 8192) + (size_t)h * 1024 + m0;
    const float thr = tau_s[lane];
#pragma unroll 4
    for (int jj = 0; jj < 64; jj++) {
        int n = jj * 16 + w;
        float v = S_s[lane * SROW + n] - thr;
        out[outbase + (size_t)n * 8192 + lane] = fmaxf(v, 0.f);
    }
}

// ---------------------------------------------------------------------------
extern "C" void kernel_launch(void* const* d_in, const int* in_sizes, int n_in,
                              void* d_out, int out_size) {
    (void)in_sizes; (void)n_in; (void)out_size;
    const float* x   = (const float*)d_in[0];
    const float* qw  = (const float*)d_in[1];
    const float* kw  = (const float*)d_in[2];
    const float* bnw = (const float*)d_in[3];
    const float* bnb = (const float*)d_in[4];
    float* out = (float*)d_out;

    cudaFuncSetAttribute(gemm_qk_mma,
                         cudaFuncAttributeMaxDynamicSharedMemorySize, QK_SMEM);
    cudaFuncSetAttribute(fused_scores_sparsemax,
                         cudaFuncAttributeMaxDynamicSharedMemorySize, FS_SMEM);

    split_inputs_kernel<<<2304, 256>>>(x, qw, kw);
    dim3 g1(4, 64, 2);
    gemm_qk_mma<<<g1, 256, QK_SMEM>>>();
    normalize_kernel<<<16384, 256>>>(bnw, bnb);
    dim3 g2(32, 64);
    fused_scores_sparsemax<<<g2, 512, FS_SMEM>>>(out);
}